// round 11
// baseline (speedup 1.0000x reference)
#include <cuda_runtime.h>
#include <cuda_bf16.h>
#include <cstdint>

#define NN 50000
#define EE 800000
#define FDIM 256
#define HEADS 4
#define HID 64
#define BNPART 256
#define NCHUNK 49                      // ceil((NN+1)/1024)

// ---------------- scratch (static device globals; allocation-free) ----------------
__device__ float  d_y1[NN * FDIM];     // linear1 output + GAT1 aggregation -> x1
__device__ float  d_h1[NN * FDIM];     // GAT1 transformed features
__device__ __nv_bfloat16 d_a_hi[NN * FDIM];   // BN(x) in bf16 hi
__device__ __nv_bfloat16 d_a_lo[NN * FDIM];   // residual lo
__device__ __nv_bfloat16 d_w_hi[2 * FDIM * FDIM];  // [mat][n][k] transposed weights
__device__ __nv_bfloat16 d_w_lo[2 * FDIM * FDIM];
__device__ float4 d_p3[NN];            // packed layer-2: (als3, h0, h1, ald3)
__device__ float  d_bnps[BNPART * FDIM];
__device__ float  d_bnpq[BNPART * FDIM];
__device__ float  d_scale[FDIM];
__device__ float  d_shift[FDIM];
__device__ int d_rowptr[NN + 1];
__device__ int d_cursor[NN];
__device__ int d_csr_src[EE];
__device__ int d_scanpre[64];
__device__ int d_scanflag[64];

__device__ __forceinline__ float lrelu(float x) { return x > 0.f ? x : 0.2f * x; }

// ---------------- BN stats (+ optional zero blocks for rowptr/scan flags) ----------------
__global__ void bn_stats(const float* __restrict__ x, int dorelu) {
    if (blockIdx.x >= BNPART) {
        int bid2 = blockIdx.x - BNPART;
        if (bid2 < 196) {
            int i = bid2 * 256 + threadIdx.x;
            if (i <= NN) d_rowptr[i] = 0;
        } else {
            if (threadIdx.x < 64) d_scanflag[threadIdx.x] = 0;
        }
        return;
    }
    const float* src = x ? x : (const float*)d_y1;
    int c = threadIdx.x;
    float s = 0.f, s2 = 0.f;
    for (int r = blockIdx.x; r < NN; r += BNPART) {
        float v = src[r * FDIM + c];
        if (dorelu) v = fmaxf(v, 0.f);
        s += v; s2 += v * v;
    }
    d_bnps[blockIdx.x * FDIM + c] = s;
    d_bnpq[blockIdx.x * FDIM + c] = s2;
}
__global__ void bn_finalize(const float* __restrict__ g, const float* __restrict__ b) {
    int c = threadIdx.x;
    float s = 0.f, q = 0.f;
    #pragma unroll 8
    for (int i = 0; i < BNPART; i++) {
        s += d_bnps[i * FDIM + c];
        q += d_bnpq[i * FDIM + c];
    }
    const float invn = 1.0f / (float)NN;
    float mu = s * invn;
    float var = q * invn - mu * mu;
    float rs = rsqrtf(var + 1e-5f);
    float sc = rs * g[c];
    d_scale[c] = sc;
    d_shift[c] = b[c] - mu * sc;
}

// ---------------- prep: BN+hi/lo conv of A, weight conv, edge histogram ----------------
#define PREP_A 12500
#define PREP_W 512
#define PREP_H 3125
__global__ void prep_k(const float* __restrict__ x,
                       const float* __restrict__ W0, const float* __restrict__ W1,
                       const int* __restrict__ ei) {
    int bid = blockIdx.x;
    int t = threadIdx.x;
    if (bid < PREP_A) {
        int i = bid * 256 + t;
        int c = (i & 63) << 2;
        float4 v = ((const float4*)x)[i];
        float4 sc = *(const float4*)&d_scale[c];
        float4 sh = *(const float4*)&d_shift[c];
        float a0 = v.x * sc.x + sh.x, a1 = v.y * sc.y + sh.y;
        float a2 = v.z * sc.z + sh.z, a3 = v.w * sc.w + sh.w;
        __nv_bfloat16 h0 = __float2bfloat16_rn(a0), h1 = __float2bfloat16_rn(a1);
        __nv_bfloat16 h2 = __float2bfloat16_rn(a2), h3 = __float2bfloat16_rn(a3);
        __nv_bfloat162* ph = (__nv_bfloat162*)d_a_hi;
        ph[i * 2]     = __nv_bfloat162(h0, h1);
        ph[i * 2 + 1] = __nv_bfloat162(h2, h3);
        __nv_bfloat162* pl = (__nv_bfloat162*)d_a_lo;
        pl[i * 2]     = __nv_bfloat162(__float2bfloat16_rn(a0 - __bfloat162float(h0)),
                                       __float2bfloat16_rn(a1 - __bfloat162float(h1)));
        pl[i * 2 + 1] = __nv_bfloat162(__float2bfloat16_rn(a2 - __bfloat162float(h2)),
                                       __float2bfloat16_rn(a3 - __bfloat162float(h3)));
    } else if (bid < PREP_A + PREP_W) {
        int i = (bid - PREP_A) * 256 + t;
        int mat = i >> 16, r = i & 65535;
        int n = r >> 8, k = r & 255;
        const float* W = mat ? W1 : W0;
        float v = W[k * 256 + n];
        __nv_bfloat16 h = __float2bfloat16_rn(v);
        d_w_hi[i] = h;
        d_w_lo[i] = __float2bfloat16_rn(v - __bfloat162float(h));
    } else {
        int e = (bid - PREP_A - PREP_W) * 256 + t;
        if (e < EE) atomicAdd(&d_rowptr[ei[EE + e] + 1], 1);
    }
}

// ---------------- single-kernel decoupled scan (49 resident blocks) + cursor init ----------------
__global__ void scan_k() {
    __shared__ int s[1024];
    __shared__ int base_s;
    int b = blockIdx.x, tid = threadIdx.x;
    int i = b * 1024 + tid;
    int v = (i <= NN) ? d_rowptr[i] : 0;
    s[tid] = v;
    __syncthreads();
    #pragma unroll
    for (int off = 1; off < 1024; off <<= 1) {
        int add = (tid >= off) ? s[tid - off] : 0;
        __syncthreads();
        s[tid] += add;
        __syncthreads();
    }
    if (tid == 0) {
        int base = 0;
        if (b > 0) {
            while (atomicAdd(&d_scanflag[b - 1], 0) == 0) { }
            __threadfence();
            base = *(volatile int*)&d_scanpre[b - 1];
        }
        *(volatile int*)&d_scanpre[b] = base + s[1023];
        __threadfence();
        atomicExch(&d_scanflag[b], 1);
        base_s = base;
    }
    __syncthreads();
    int val = s[tid] + base_s;
    if (i <= NN) {
        d_rowptr[i] = val;
        if (i < NN) d_cursor[i] = val;
    }
}
__global__ void scatter_k(const int* __restrict__ ei) {
    int e = blockIdx.x * blockDim.x + threadIdx.x;
    if (e >= EE) return;
    int s = ei[e], t = ei[EE + e];
    int pos = atomicAdd(&d_cursor[t], 1);
    d_csr_src[pos] = s;
}

// ---------------- bf16 split tensor-core GEMM: 4-stage deep pipeline, BK=16 ----------------
#define SLDA 24
#define PLANE (128 * SLDA * 2)
#define STG (4 * PLANE)
#define GSMEM (4 * STG)

__device__ __forceinline__ void mma16816(float* d, const uint32_t* a, uint32_t b0, uint32_t b1) {
    asm volatile("mma.sync.aligned.m16n8k16.row.col.f32.bf16.bf16.f32 "
                 "{%0,%1,%2,%3}, {%4,%5,%6,%7}, {%8,%9}, {%0,%1,%2,%3};"
                 : "+f"(d[0]), "+f"(d[1]), "+f"(d[2]), "+f"(d[3])
                 : "r"(a[0]), "r"(a[1]), "r"(a[2]), "r"(a[3]), "r"(b0), "r"(b1));
}
__device__ __forceinline__ void ldsm4(uint32_t* r, uint32_t addr) {
    asm volatile("ldmatrix.sync.aligned.m8n8.x4.shared.b16 {%0,%1,%2,%3}, [%4];"
                 : "=r"(r[0]), "=r"(r[1]), "=r"(r[2]), "=r"(r[3]) : "r"(addr));
}
__device__ __forceinline__ void cpa16(uint32_t saddr, const void* gaddr, int bytes) {
    asm volatile("cp.async.cg.shared.global [%0], [%1], 16, %2;"
                 :: "r"(saddr), "l"(gaddr), "r"(bytes));
}

extern __shared__ char dynsmem[];

__global__ void __launch_bounds__(256, 2)
gemm_bf16(const float* __restrict__ b0a, const float* __restrict__ b0b) {
    int t = threadIdx.x;
    int mat = blockIdx.x >> 1;
    int n0 = (blockIdx.x & 1) * 128;
    int m0 = blockIdx.y * 128;
    const __nv_bfloat16* Bh = d_w_hi + mat * 65536;
    const __nv_bfloat16* Bl = d_w_lo + mat * 65536;
    float* C = mat ? d_h1 : d_y1;

    int lrow = t >> 1, seg = t & 1;
    int gm = m0 + lrow;
    bool aok = gm < NN;
    int gmc = aok ? gm : 0;
    int abytes = aok ? 16 : 0;

    const char* gAh = (const char*)(d_a_hi + (size_t)gmc * 256) + seg * 16;
    const char* gAl = (const char*)(d_a_lo + (size_t)gmc * 256) + seg * 16;
    const char* gBh = (const char*)(Bh + (size_t)(n0 + lrow) * 256) + seg * 16;
    const char* gBl = (const char*)(Bl + (size_t)(n0 + lrow) * 256) + seg * 16;

    uint32_t smem0 = (uint32_t)__cvta_generic_to_shared(dynsmem);
    uint32_t rowoff = (uint32_t)(lrow * 48 + seg * 16);

    auto issue = [&](int slab, int buf) {
        uint32_t base = smem0 + buf * STG + rowoff;
        int go = slab * 32;
        cpa16(base,             gAh + go, abytes);
        cpa16(base + PLANE,     gAl + go, abytes);
        cpa16(base + 2 * PLANE, gBh + go, 16);
        cpa16(base + 3 * PLANE, gBl + go, 16);
        asm volatile("cp.async.commit_group;");
    };

    issue(0, 0);
    issue(1, 1);
    issue(2, 2);

    int wid = t >> 5, lane = t & 31;
    int wm0 = (wid & 1) * 64, wn0 = (wid >> 1) * 32;
    float acc[4][4][4] = {};

    int a_r = (lane & 15);
    int a_c = (lane >> 4) << 3;
    int b_r = (lane & 7) + ((lane & 16) ? 8 : 0);
    int b_c = (lane & 8) ? 8 : 0;

    for (int s = 0; s < 16; s++) {
        asm volatile("cp.async.wait_group 2;");
        __syncthreads();
        if (s + 3 < 16) issue(s + 3, (s + 3) & 3);
        else            asm volatile("cp.async.commit_group;");

        uint32_t sAu = smem0 + (s & 3) * STG;
        uint32_t sBu = sAu + 2 * PLANE;
        uint32_t bh[2][4], bl[2][4];
        #pragma unroll
        for (int jp = 0; jp < 2; jp++) {
            uint32_t addr = sBu + (uint32_t)(((wn0 + jp * 16 + b_r) * SLDA + b_c) * 2);
            ldsm4(bh[jp], addr);
            ldsm4(bl[jp], addr + PLANE);
        }
        #pragma unroll
        for (int i = 0; i < 4; i++) {
            uint32_t ah[4], al[4];
            uint32_t addr = sAu + (uint32_t)(((wm0 + i * 16 + a_r) * SLDA + a_c) * 2);
            ldsm4(ah, addr);
            ldsm4(al, addr + PLANE);
            #pragma unroll
            for (int j = 0; j < 4; j++) {
                int jp = j >> 1, o = (j & 1) * 2;
                mma16816(acc[i][j], ah, bh[jp][o], bh[jp][o + 1]);
                mma16816(acc[i][j], ah, bl[jp][o], bl[jp][o + 1]);
                mma16816(acc[i][j], al, bh[jp][o], bh[jp][o + 1]);
            }
        }
    }

    int g = lane >> 2, tq = lane & 3;
    #pragma unroll
    for (int j = 0; j < 4; j++) {
        int gcol = n0 + wn0 + j * 8 + tq * 2;
        float bx = 0.f, by = 0.f;
        if (!mat) {
            bx = b0a[gcol] + b0b[gcol];
            by = b0a[gcol + 1] + b0b[gcol + 1];
        }
        #pragma unroll
        for (int i = 0; i < 4; i++) {
            int r0 = m0 + wm0 + i * 16 + g;
            if (r0 < NN)
                *(float2*)&C[(size_t)r0 * 256 + gcol] =
                    make_float2(acc[i][j][0] + bx, acc[i][j][1] + by);
            int r1 = r0 + 8;
            if (r1 < NN)
                *(float2*)&C[(size_t)r1 * 256 + gcol] =
                    make_float2(acc[i][j][2] + bx, acc[i][j][3] + by);
        }
    }
}

// ---------------- fused layer-1 GAT: on-the-fly logits + softmax + aggregation ----------------
// warp/dst; als computed from the gathered row (already in regs), ald from dst row.
__global__ void gat1_warp(const float* __restrict__ asrc, const float* __restrict__ adst) {
    int d = (blockIdx.x * blockDim.x + threadIdx.x) >> 5;
    int lane = threadIdx.x & 31;
    if (d >= NN) return;
    int b = d_rowptr[d], e = d_rowptr[d + 1];
    if (b == e) return;
    int grp = lane & ~7;               // 8-lane group leader (same head)
    int coff = lane * 8;               // my 8 channels (global)
    const float* asl = asrc + (coff & 255) / 64 * 64 + (lane & 7) * 8;
    const float* adl = adst + (coff & 255) / 64 * 64 + (lane & 7) * 8;
    float4 as0 = *(const float4*)asl, as1 = *(const float4*)(asl + 4);
    float4 ad0 = *(const float4*)adl, ad1 = *(const float4*)(adl + 4);
    const float* __restrict__ hp = (const float*)d_h1;

    // ald for this dst (per my head)
    float4 r0 = *(const float4*)&hp[(size_t)d * 256 + coff];
    float4 r1 = *(const float4*)&hp[(size_t)d * 256 + coff + 4];
    float pal = r0.x*ad0.x + r0.y*ad0.y + r0.z*ad0.z + r0.w*ad0.w
              + r1.x*ad1.x + r1.y*ad1.y + r1.z*ad1.z + r1.w*ad1.w;
    pal += __shfl_down_sync(0xffffffffu, pal, 4, 8);
    pal += __shfl_down_sync(0xffffffffu, pal, 2, 8);
    pal += __shfl_down_sync(0xffffffffu, pal, 1, 8);
    float ald = __shfl_sync(0xffffffffu, pal, grp);

    float4 acc0 = make_float4(0.f, 0.f, 0.f, 0.f);
    float4 acc1 = make_float4(0.f, 0.f, 0.f, 0.f);
    float den = 0.f;

    for (int c0 = b; c0 < e; c0 += 32) {
        int cnt = min(32, e - c0);
        int src = (lane < cnt) ? d_csr_src[c0 + lane] : 0;
        #pragma unroll 4
        for (int j = 0; j < cnt; j++) {
            int sj = __shfl_sync(0xffffffffu, src, j);
            const float4* hv = (const float4*)&hp[(size_t)sj * 256 + coff];
            float4 v0 = hv[0], v1 = hv[1];
            float ps = v0.x*as0.x + v0.y*as0.y + v0.z*as0.z + v0.w*as0.w
                     + v1.x*as1.x + v1.y*as1.y + v1.z*as1.z + v1.w*as1.w;
            ps += __shfl_down_sync(0xffffffffu, ps, 4, 8);
            ps += __shfl_down_sync(0xffffffffu, ps, 2, 8);
            ps += __shfl_down_sync(0xffffffffu, ps, 1, 8);
            float als = __shfl_sync(0xffffffffu, ps, grp);
            float w = __expf(lrelu(als + ald));
            den += w;
            acc0.x += w * v0.x; acc0.y += w * v0.y;
            acc0.z += w * v0.z; acc0.w += w * v0.w;
            acc1.x += w * v1.x; acc1.y += w * v1.y;
            acc1.z += w * v1.z; acc1.w += w * v1.w;
        }
    }
    float r = 1.f / (den + 1e-16f);
    float4* yp = (float4*)&d_y1[(size_t)d * 256 + coff];
    float4 o0 = yp[0], o1 = yp[1];
    o0.x += acc0.x * r; o0.y += acc0.y * r; o0.z += acc0.z * r; o0.w += acc0.w * r;
    o1.x += acc1.x * r; o1.y += acc1.y * r; o1.z += acc1.z * r; o1.w += acc1.w * r;
    yp[0] = o0; yp[1] = o1;
}

// ---------------- layer 2: fused relu+BN + linear3 + GAT2 features/logits ----------------
__global__ void layer2_row(const float* __restrict__ lin3W, const float* __restrict__ lin3b,
                           const float* __restrict__ con3W, const float* __restrict__ asrc,
                           const float* __restrict__ adst, const float* __restrict__ con3b,
                           float* __restrict__ out) {
    int warp = (blockIdx.x * blockDim.x + threadIdx.x) >> 5;
    int lane = threadIdx.x & 31;
    if (warp >= NN) return;
    const float* row = (const float*)d_y1 + (size_t)warp * 256;
    float y0 = 0.f, y1v = 0.f, h0 = 0.f, h1v = 0.f;
    #pragma unroll
    for (int q = 0; q < 8; q++) {
        int c = lane + q * 32;
        float v = fmaxf(row[c], 0.f) * d_scale[c] + d_shift[c];
        y0  += v * lin3W[c * 2];
        y1v += v * lin3W[c * 2 + 1];
        h0  += v * con3W[c * 2];
        h1v += v * con3W[c * 2 + 1];
    }
    #pragma unroll
    for (int off = 16; off > 0; off >>= 1) {
        y0  += __shfl_xor_sync(0xffffffff, y0,  off);
        y1v += __shfl_xor_sync(0xffffffff, y1v, off);
        h0  += __shfl_xor_sync(0xffffffff, h0,  off);
        h1v += __shfl_xor_sync(0xffffffff, h1v, off);
    }
    if (lane == 0) {
        out[warp * 2]     = y0  + lin3b[0] + con3b[0];
        out[warp * 2 + 1] = y1v + lin3b[1] + con3b[1];
        d_p3[warp] = make_float4(h0 * asrc[0] + h1v * asrc[1],
                                 h0, h1v,
                                 h0 * adst[0] + h1v * adst[1]);
    }
}

// ---------------- layer-2 GAT + final relu (warp/dst, single LDG.128 per edge) ----------------
__global__ void gat_l2(float* __restrict__ out) {
    int d = (blockIdx.x * blockDim.x + threadIdx.x) >> 5;
    int lane = threadIdx.x & 31;
    if (d >= NN) return;
    int b = d_rowptr[d], e = d_rowptr[d + 1];
    float ald = d_p3[d].w;
    float den = 0.f, m0 = 0.f, m1 = 0.f;
    for (int j = b + lane; j < e; j += 32) {
        int src = d_csr_src[j];
        float4 p = d_p3[src];
        float ex = __expf(lrelu(p.x + ald));
        den += ex; m0 += ex * p.y; m1 += ex * p.z;
    }
    #pragma unroll
    for (int off = 16; off > 0; off >>= 1) {
        den += __shfl_xor_sync(0xffffffff, den, off);
        m0  += __shfl_xor_sync(0xffffffff, m0,  off);
        m1  += __shfl_xor_sync(0xffffffff, m1,  off);
    }
    if (lane == 0) {
        float r = 1.f / (den + 1e-16f);
        out[d * 2]     = fmaxf(out[d * 2]     + m0 * r, 0.f);
        out[d * 2 + 1] = fmaxf(out[d * 2 + 1] + m1 * r, 0.f);
    }
}

// ---------------- launch ----------------
extern "C" void kernel_launch(void* const* d_in, const int* in_sizes, int n_in,
                              void* d_out, int out_size) {
    const float* x         = (const float*)d_in[0];
    const int*   ei        = (const int*)d_in[1];
    const float* bn1_g     = (const float*)d_in[2];
    const float* bn1_b     = (const float*)d_in[3];
    const float* lin1_W    = (const float*)d_in[4];
    const float* lin1_b    = (const float*)d_in[5];
    const float* con1_W    = (const float*)d_in[6];
    const float* con1_asrc = (const float*)d_in[7];
    const float* con1_adst = (const float*)d_in[8];
    const float* con1_b    = (const float*)d_in[9];
    const float* bn3_g     = (const float*)d_in[10];
    const float* bn3_b     = (const float*)d_in[11];
    const float* lin3_W    = (const float*)d_in[12];
    const float* lin3_b    = (const float*)d_in[13];
    const float* con3_W    = (const float*)d_in[14];
    const float* con3_asrc = (const float*)d_in[15];
    const float* con3_adst = (const float*)d_in[16];
    const float* con3_b    = (const float*)d_in[17];
    float* out = (float*)d_out;

    cudaFuncSetAttribute(gemm_bf16, cudaFuncAttributeMaxDynamicSharedMemorySize, GSMEM);

    // 1-3: BN1 stats (+zero rowptr/scanflags), finalize, fused prep (+edge histogram)
    bn_stats<<<BNPART + 197, 256>>>(x, 0);
    bn_finalize<<<1, 256>>>(bn1_g, bn1_b);
    prep_k<<<PREP_A + PREP_W + PREP_H, 256>>>(x, lin1_W, con1_W, ei);

    // 4 (ncu-profiled slot): the dual GEMM
    gemm_bf16<<<dim3(4, (NN + 127) / 128), 256, GSMEM>>>(lin1_b, con1_b);

    // 5-6: single-kernel scan (+cursor init), scatter
    scan_k<<<NCHUNK, 1024>>>();
    scatter_k<<<(EE + 255) / 256, 256>>>(ei);

    // 7: fully fused GAT1 (logits + softmax + aggregation)
    gat1_warp<<<(NN + 7) / 8, 256>>>(con1_asrc, con1_adst);

    // 8-9: BN3 stats (relu fused into read), finalize
    bn_stats<<<BNPART, 256>>>(nullptr, 1);
    bn_finalize<<<1, 256>>>(bn3_g, bn3_b);

    // 10-11: layer 2
    layer2_row<<<(NN + 7) / 8, 256>>>(lin3_W, lin3_b, con3_W, con3_asrc, con3_adst, con3_b, out);
    gat_l2<<<(NN + 7) / 8, 256>>>(out);
}

// round 12
// speedup vs baseline: 1.0101x; 1.0101x over previous
#include <cuda_runtime.h>
#include <cuda_bf16.h>
#include <cstdint>

#define NN 50000
#define EE 800000
#define FDIM 256
#define HEADS 4
#define HID 64
#define BNPART 256
#define NCHUNK 49                      // ceil((NN+1)/1024)

// ---------------- scratch (static device globals; allocation-free) ----------------
__device__ float  d_y1[NN * FDIM];     // linear1 output + GAT1 aggregation -> x1
__device__ float  d_h1[NN * FDIM];     // GAT1 transformed features
__device__ __nv_bfloat16 d_a_hi[NN * FDIM];   // BN(x) in bf16 hi
__device__ __nv_bfloat16 d_a_lo[NN * FDIM];   // residual lo
__device__ __nv_bfloat16 d_w_hi[2 * FDIM * FDIM];  // [mat][n][k] transposed weights
__device__ __nv_bfloat16 d_w_lo[2 * FDIM * FDIM];
__device__ float4 d_als1[NN];
__device__ float4 d_ald1[NN];
__device__ float4 d_p3[NN];            // packed layer-2: (als3, h0, h1, ald3)
__device__ float  d_bnps[BNPART * FDIM];
__device__ float  d_bnpq[BNPART * FDIM];
__device__ float  d_scale[FDIM];
__device__ float  d_shift[FDIM];
__device__ int d_rowptr[NN + 1];
__device__ int d_cursor[NN];
__device__ int d_csr_src[EE];
__device__ int d_scanpre[64];
__device__ int d_scanflag[64];

__device__ __forceinline__ float lrelu(float x) { return x > 0.f ? x : 0.2f * x; }

// ---------------- BN stats (+ optional zero blocks for rowptr/scan flags) ----------------
__global__ void bn_stats(const float* __restrict__ x, int dorelu) {
    if (blockIdx.x >= BNPART) {
        int bid2 = blockIdx.x - BNPART;
        if (bid2 < 196) {
            int i = bid2 * 256 + threadIdx.x;
            if (i <= NN) d_rowptr[i] = 0;
        } else {
            if (threadIdx.x < 64) d_scanflag[threadIdx.x] = 0;
        }
        return;
    }
    const float* src = x ? x : (const float*)d_y1;
    int c = threadIdx.x;
    float s = 0.f, s2 = 0.f;
    for (int r = blockIdx.x; r < NN; r += BNPART) {
        float v = src[r * FDIM + c];
        if (dorelu) v = fmaxf(v, 0.f);
        s += v; s2 += v * v;
    }
    d_bnps[blockIdx.x * FDIM + c] = s;
    d_bnpq[blockIdx.x * FDIM + c] = s2;
}
__global__ void bn_finalize(const float* __restrict__ g, const float* __restrict__ b) {
    int c = threadIdx.x;
    float s = 0.f, q = 0.f;
    #pragma unroll 8
    for (int i = 0; i < BNPART; i++) {
        s += d_bnps[i * FDIM + c];
        q += d_bnpq[i * FDIM + c];
    }
    const float invn = 1.0f / (float)NN;
    float mu = s * invn;
    float var = q * invn - mu * mu;
    float rs = rsqrtf(var + 1e-5f);
    float sc = rs * g[c];
    d_scale[c] = sc;
    d_shift[c] = b[c] - mu * sc;
}

// ---------------- prep: BN+hi/lo conv of A, weight conv, edge histogram ----------------
#define PREP_A 12500
#define PREP_W 512
#define PREP_H 3125
__global__ void prep_k(const float* __restrict__ x,
                       const float* __restrict__ W0, const float* __restrict__ W1,
                       const int* __restrict__ ei) {
    int bid = blockIdx.x;
    int t = threadIdx.x;
    if (bid < PREP_A) {
        int i = bid * 256 + t;
        int c = (i & 63) << 2;
        float4 v = ((const float4*)x)[i];
        float4 sc = *(const float4*)&d_scale[c];
        float4 sh = *(const float4*)&d_shift[c];
        float a0 = v.x * sc.x + sh.x, a1 = v.y * sc.y + sh.y;
        float a2 = v.z * sc.z + sh.z, a3 = v.w * sc.w + sh.w;
        __nv_bfloat16 h0 = __float2bfloat16_rn(a0), h1 = __float2bfloat16_rn(a1);
        __nv_bfloat16 h2 = __float2bfloat16_rn(a2), h3 = __float2bfloat16_rn(a3);
        __nv_bfloat162* ph = (__nv_bfloat162*)d_a_hi;
        ph[i * 2]     = __nv_bfloat162(h0, h1);
        ph[i * 2 + 1] = __nv_bfloat162(h2, h3);
        __nv_bfloat162* pl = (__nv_bfloat162*)d_a_lo;
        pl[i * 2]     = __nv_bfloat162(__float2bfloat16_rn(a0 - __bfloat162float(h0)),
                                       __float2bfloat16_rn(a1 - __bfloat162float(h1)));
        pl[i * 2 + 1] = __nv_bfloat162(__float2bfloat16_rn(a2 - __bfloat162float(h2)),
                                       __float2bfloat16_rn(a3 - __bfloat162float(h3)));
    } else if (bid < PREP_A + PREP_W) {
        int i = (bid - PREP_A) * 256 + t;
        int mat = i >> 16, r = i & 65535;
        int n = r >> 8, k = r & 255;
        const float* W = mat ? W1 : W0;
        float v = W[k * 256 + n];
        __nv_bfloat16 h = __float2bfloat16_rn(v);
        d_w_hi[i] = h;
        d_w_lo[i] = __float2bfloat16_rn(v - __bfloat162float(h));
    } else {
        int e = (bid - PREP_A - PREP_W) * 256 + t;
        if (e < EE) atomicAdd(&d_rowptr[ei[EE + e] + 1], 1);
    }
}

// ---------------- single-kernel decoupled scan (49 resident blocks) + cursor init ----------------
__global__ void scan_k() {
    __shared__ int s[1024];
    __shared__ int base_s;
    int b = blockIdx.x, tid = threadIdx.x;
    int i = b * 1024 + tid;
    int v = (i <= NN) ? d_rowptr[i] : 0;
    s[tid] = v;
    __syncthreads();
    #pragma unroll
    for (int off = 1; off < 1024; off <<= 1) {
        int add = (tid >= off) ? s[tid - off] : 0;
        __syncthreads();
        s[tid] += add;
        __syncthreads();
    }
    if (tid == 0) {
        int base = 0;
        if (b > 0) {
            while (atomicAdd(&d_scanflag[b - 1], 0) == 0) { }
            __threadfence();
            base = *(volatile int*)&d_scanpre[b - 1];
        }
        *(volatile int*)&d_scanpre[b] = base + s[1023];
        __threadfence();
        atomicExch(&d_scanflag[b], 1);
        base_s = base;
    }
    __syncthreads();
    int val = s[tid] + base_s;
    if (i <= NN) {
        d_rowptr[i] = val;
        if (i < NN) d_cursor[i] = val;
    }
}
__global__ void scatter_k(const int* __restrict__ ei) {
    int e = blockIdx.x * blockDim.x + threadIdx.x;
    if (e >= EE) return;
    int s = ei[e], t = ei[EE + e];
    int pos = atomicAdd(&d_cursor[t], 1);
    d_csr_src[pos] = s;
}

// ---------------- bf16 split tensor-core GEMM: 4-stage deep pipeline, BK=16 ----------------
#define SLDA 24
#define PLANE (128 * SLDA * 2)
#define STG (4 * PLANE)
#define GSMEM (4 * STG)

__device__ __forceinline__ void mma16816(float* d, const uint32_t* a, uint32_t b0, uint32_t b1) {
    asm volatile("mma.sync.aligned.m16n8k16.row.col.f32.bf16.bf16.f32 "
                 "{%0,%1,%2,%3}, {%4,%5,%6,%7}, {%8,%9}, {%0,%1,%2,%3};"
                 : "+f"(d[0]), "+f"(d[1]), "+f"(d[2]), "+f"(d[3])
                 : "r"(a[0]), "r"(a[1]), "r"(a[2]), "r"(a[3]), "r"(b0), "r"(b1));
}
__device__ __forceinline__ void ldsm4(uint32_t* r, uint32_t addr) {
    asm volatile("ldmatrix.sync.aligned.m8n8.x4.shared.b16 {%0,%1,%2,%3}, [%4];"
                 : "=r"(r[0]), "=r"(r[1]), "=r"(r[2]), "=r"(r[3]) : "r"(addr));
}
__device__ __forceinline__ void cpa16(uint32_t saddr, const void* gaddr, int bytes) {
    asm volatile("cp.async.cg.shared.global [%0], [%1], 16, %2;"
                 :: "r"(saddr), "l"(gaddr), "r"(bytes));
}

extern __shared__ char dynsmem[];

__global__ void __launch_bounds__(256, 2)
gemm_bf16(const float* __restrict__ b0a, const float* __restrict__ b0b) {
    int t = threadIdx.x;
    int mat = blockIdx.x >> 1;
    int n0 = (blockIdx.x & 1) * 128;
    int m0 = blockIdx.y * 128;
    const __nv_bfloat16* Bh = d_w_hi + mat * 65536;
    const __nv_bfloat16* Bl = d_w_lo + mat * 65536;
    float* C = mat ? d_h1 : d_y1;

    int lrow = t >> 1, seg = t & 1;
    int gm = m0 + lrow;
    bool aok = gm < NN;
    int gmc = aok ? gm : 0;
    int abytes = aok ? 16 : 0;

    const char* gAh = (const char*)(d_a_hi + (size_t)gmc * 256) + seg * 16;
    const char* gAl = (const char*)(d_a_lo + (size_t)gmc * 256) + seg * 16;
    const char* gBh = (const char*)(Bh + (size_t)(n0 + lrow) * 256) + seg * 16;
    const char* gBl = (const char*)(Bl + (size_t)(n0 + lrow) * 256) + seg * 16;

    uint32_t smem0 = (uint32_t)__cvta_generic_to_shared(dynsmem);
    uint32_t rowoff = (uint32_t)(lrow * 48 + seg * 16);

    auto issue = [&](int slab, int buf) {
        uint32_t base = smem0 + buf * STG + rowoff;
        int go = slab * 32;
        cpa16(base,             gAh + go, abytes);
        cpa16(base + PLANE,     gAl + go, abytes);
        cpa16(base + 2 * PLANE, gBh + go, 16);
        cpa16(base + 3 * PLANE, gBl + go, 16);
        asm volatile("cp.async.commit_group;");
    };

    issue(0, 0);
    issue(1, 1);
    issue(2, 2);

    int wid = t >> 5, lane = t & 31;
    int wm0 = (wid & 1) * 64, wn0 = (wid >> 1) * 32;
    float acc[4][4][4] = {};

    int a_r = (lane & 15);
    int a_c = (lane >> 4) << 3;
    int b_r = (lane & 7) + ((lane & 16) ? 8 : 0);
    int b_c = (lane & 8) ? 8 : 0;

    for (int s = 0; s < 16; s++) {
        asm volatile("cp.async.wait_group 2;");
        __syncthreads();
        if (s + 3 < 16) issue(s + 3, (s + 3) & 3);
        else            asm volatile("cp.async.commit_group;");

        uint32_t sAu = smem0 + (s & 3) * STG;
        uint32_t sBu = sAu + 2 * PLANE;
        uint32_t bh[2][4], bl[2][4];
        #pragma unroll
        for (int jp = 0; jp < 2; jp++) {
            uint32_t addr = sBu + (uint32_t)(((wn0 + jp * 16 + b_r) * SLDA + b_c) * 2);
            ldsm4(bh[jp], addr);
            ldsm4(bl[jp], addr + PLANE);
        }
        #pragma unroll
        for (int i = 0; i < 4; i++) {
            uint32_t ah[4], al[4];
            uint32_t addr = sAu + (uint32_t)(((wm0 + i * 16 + a_r) * SLDA + a_c) * 2);
            ldsm4(ah, addr);
            ldsm4(al, addr + PLANE);
            #pragma unroll
            for (int j = 0; j < 4; j++) {
                int jp = j >> 1, o = (j & 1) * 2;
                mma16816(acc[i][j], ah, bh[jp][o], bh[jp][o + 1]);
                mma16816(acc[i][j], ah, bl[jp][o], bl[jp][o + 1]);
                mma16816(acc[i][j], al, bh[jp][o], bh[jp][o + 1]);
            }
        }
    }

    int g = lane >> 2, tq = lane & 3;
    #pragma unroll
    for (int j = 0; j < 4; j++) {
        int gcol = n0 + wn0 + j * 8 + tq * 2;
        float bx = 0.f, by = 0.f;
        if (!mat) {
            bx = b0a[gcol] + b0b[gcol];
            by = b0a[gcol + 1] + b0b[gcol + 1];
        }
        #pragma unroll
        for (int i = 0; i < 4; i++) {
            int r0 = m0 + wm0 + i * 16 + g;
            if (r0 < NN)
                *(float2*)&C[(size_t)r0 * 256 + gcol] =
                    make_float2(acc[i][j][0] + bx, acc[i][j][1] + by);
            int r1 = r0 + 8;
            if (r1 < NN)
                *(float2*)&C[(size_t)r1 * 256 + gcol] =
                    make_float2(acc[i][j][2] + bx, acc[i][j][3] + by);
        }
    }
}

// ---------------- attention logit contributions (layer 1): warp/node ----------------
__global__ void compute_al(const float* __restrict__ asrc, const float* __restrict__ adst) {
    int warp = (blockIdx.x * blockDim.x + threadIdx.x) >> 5;
    int lane = threadIdx.x & 31;
    if (warp >= NN) return;
    const float4* hr = (const float4*)&d_h1[(size_t)warp * 256];
    int head = lane >> 3;
    float s = 0.f, d = 0.f;
    #pragma unroll
    for (int q = 0; q < 2; q++) {
        float4 hv = hr[lane * 2 + q];
        int cbase = (lane * 8 + q * 4) & 63;
        const float* as = asrc + head * 64 + cbase;
        const float* ad = adst + head * 64 + cbase;
        s += hv.x * as[0] + hv.y * as[1] + hv.z * as[2] + hv.w * as[3];
        d += hv.x * ad[0] + hv.y * ad[1] + hv.z * ad[2] + hv.w * ad[3];
    }
    #pragma unroll
    for (int off = 4; off > 0; off >>= 1) {
        s += __shfl_down_sync(0xffffffff, s, off);
        d += __shfl_down_sync(0xffffffff, d, off);
    }
    if ((lane & 7) == 0) {
        ((float*)&d_als1[warp])[head] = s;
        ((float*)&d_ald1[warp])[head] = d;
    }
}

// ---------------- layer-1 GAT: warp/dst, shfl-broadcast of precomputed ex ----------------
__global__ void gat1_warp() {
    int d = (blockIdx.x * blockDim.x + threadIdx.x) >> 5;
    int lane = threadIdx.x & 31;
    if (d >= NN) return;
    int b = d_rowptr[d], e = d_rowptr[d + 1];
    if (b == e) return;
    float4 ald = d_ald1[d];
    int h = lane >> 3;
    int coff = lane * 8;
    float4 acc0 = make_float4(0.f, 0.f, 0.f, 0.f);
    float4 acc1 = make_float4(0.f, 0.f, 0.f, 0.f);
    float den = 0.f;
    const float* __restrict__ hp = (const float*)d_h1;

    for (int c0 = b; c0 < e; c0 += 32) {
        int cnt = min(32, e - c0);
        int src = 0;
        float4 ex = make_float4(0.f, 0.f, 0.f, 0.f);
        if (lane < cnt) {
            src = d_csr_src[c0 + lane];
            float4 a = d_als1[src];
            ex.x = __expf(lrelu(a.x + ald.x));
            ex.y = __expf(lrelu(a.y + ald.y));
            ex.z = __expf(lrelu(a.z + ald.z));
            ex.w = __expf(lrelu(a.w + ald.w));
        }
        #pragma unroll 4
        for (int j = 0; j < cnt; j++) {
            int   sj = __shfl_sync(0xffffffffu, src,  j);
            float e0 = __shfl_sync(0xffffffffu, ex.x, j);
            float e1 = __shfl_sync(0xffffffffu, ex.y, j);
            float e2 = __shfl_sync(0xffffffffu, ex.z, j);
            float e3 = __shfl_sync(0xffffffffu, ex.w, j);
            float w = (h == 0) ? e0 : (h == 1) ? e1 : (h == 2) ? e2 : e3;
            den += w;
            const float4* hv = (const float4*)&hp[(size_t)sj * 256 + coff];
            float4 v0 = hv[0], v1 = hv[1];
            acc0.x += w * v0.x; acc0.y += w * v0.y;
            acc0.z += w * v0.z; acc0.w += w * v0.w;
            acc1.x += w * v1.x; acc1.y += w * v1.y;
            acc1.z += w * v1.z; acc1.w += w * v1.w;
        }
    }
    float r = 1.f / (den + 1e-16f);
    float4* yp = (float4*)&d_y1[(size_t)d * 256 + coff];
    float4 o0 = yp[0], o1 = yp[1];
    o0.x += acc0.x * r; o0.y += acc0.y * r; o0.z += acc0.z * r; o0.w += acc0.w * r;
    o1.x += acc1.x * r; o1.y += acc1.y * r; o1.z += acc1.z * r; o1.w += acc1.w * r;
    yp[0] = o0; yp[1] = o1;
}

// ---------------- layer 2: fused relu+BN + linear3 + GAT2 features/logits ----------------
__global__ void layer2_row(const float* __restrict__ lin3W, const float* __restrict__ lin3b,
                           const float* __restrict__ con3W, const float* __restrict__ asrc,
                           const float* __restrict__ adst, const float* __restrict__ con3b,
                           float* __restrict__ out) {
    int warp = (blockIdx.x * blockDim.x + threadIdx.x) >> 5;
    int lane = threadIdx.x & 31;
    if (warp >= NN) return;
    const float* row = (const float*)d_y1 + (size_t)warp * 256;
    float y0 = 0.f, y1v = 0.f, h0 = 0.f, h1v = 0.f;
    #pragma unroll
    for (int q = 0; q < 8; q++) {
        int c = lane + q * 32;
        float v = fmaxf(row[c], 0.f) * d_scale[c] + d_shift[c];
        y0  += v * lin3W[c * 2];
        y1v += v * lin3W[c * 2 + 1];
        h0  += v * con3W[c * 2];
        h1v += v * con3W[c * 2 + 1];
    }
    #pragma unroll
    for (int off = 16; off > 0; off >>= 1) {
        y0  += __shfl_xor_sync(0xffffffff, y0,  off);
        y1v += __shfl_xor_sync(0xffffffff, y1v, off);
        h0  += __shfl_xor_sync(0xffffffff, h0,  off);
        h1v += __shfl_xor_sync(0xffffffff, h1v, off);
    }
    if (lane == 0) {
        out[warp * 2]     = y0  + lin3b[0] + con3b[0];
        out[warp * 2 + 1] = y1v + lin3b[1] + con3b[1];
        d_p3[warp] = make_float4(h0 * asrc[0] + h1v * asrc[1],
                                 h0, h1v,
                                 h0 * adst[0] + h1v * adst[1]);
    }
}

// ---------------- layer-2 GAT + final relu (warp/dst, single LDG.128 per edge) ----------------
__global__ void gat_l2(float* __restrict__ out) {
    int d = (blockIdx.x * blockDim.x + threadIdx.x) >> 5;
    int lane = threadIdx.x & 31;
    if (d >= NN) return;
    int b = d_rowptr[d], e = d_rowptr[d + 1];
    float ald = d_p3[d].w;
    float den = 0.f, m0 = 0.f, m1 = 0.f;
    for (int j = b + lane; j < e; j += 32) {
        int src = d_csr_src[j];
        float4 p = d_p3[src];
        float ex = __expf(lrelu(p.x + ald));
        den += ex; m0 += ex * p.y; m1 += ex * p.z;
    }
    #pragma unroll
    for (int off = 16; off > 0; off >>= 1) {
        den += __shfl_xor_sync(0xffffffff, den, off);
        m0  += __shfl_xor_sync(0xffffffff, m0,  off);
        m1  += __shfl_xor_sync(0xffffffff, m1,  off);
    }
    if (lane == 0) {
        float r = 1.f / (den + 1e-16f);
        out[d * 2]     = fmaxf(out[d * 2]     + m0 * r, 0.f);
        out[d * 2 + 1] = fmaxf(out[d * 2 + 1] + m1 * r, 0.f);
    }
}

// ---------------- launch ----------------
extern "C" void kernel_launch(void* const* d_in, const int* in_sizes, int n_in,
                              void* d_out, int out_size) {
    const float* x         = (const float*)d_in[0];
    const int*   ei        = (const int*)d_in[1];
    const float* bn1_g     = (const float*)d_in[2];
    const float* bn1_b     = (const float*)d_in[3];
    const float* lin1_W    = (const float*)d_in[4];
    const float* lin1_b    = (const float*)d_in[5];
    const float* con1_W    = (const float*)d_in[6];
    const float* con1_asrc = (const float*)d_in[7];
    const float* con1_adst = (const float*)d_in[8];
    const float* con1_b    = (const float*)d_in[9];
    const float* bn3_g     = (const float*)d_in[10];
    const float* bn3_b     = (const float*)d_in[11];
    const float* lin3_W    = (const float*)d_in[12];
    const float* lin3_b    = (const float*)d_in[13];
    const float* con3_W    = (const float*)d_in[14];
    const float* con3_asrc = (const float*)d_in[15];
    const float* con3_adst = (const float*)d_in[16];
    const float* con3_b    = (const float*)d_in[17];
    float* out = (float*)d_out;

    cudaFuncSetAttribute(gemm_bf16, cudaFuncAttributeMaxDynamicSharedMemorySize, GSMEM);

    // 1-3: BN1 stats (+zero rowptr/scanflags), finalize, fused prep (+edge histogram)
    bn_stats<<<BNPART + 197, 256>>>(x, 0);
    bn_finalize<<<1, 256>>>(bn1_g, bn1_b);
    prep_k<<<PREP_A + PREP_W + PREP_H, 256>>>(x, lin1_W, con1_W, ei);

    // 4 (ncu-profiled slot): the dual GEMM
    gemm_bf16<<<dim3(4, (NN + 127) / 128), 256, GSMEM>>>(lin1_b, con1_b);

    // 5-6: single-kernel scan (+cursor init), scatter
    scan_k<<<NCHUNK, 1024>>>();
    scatter_k<<<(EE + 255) / 256, 256>>>(ei);

    // 7-8: GAT1 — per-node logits, then warp-per-dst softmax+aggregate
    compute_al<<<(NN + 7) / 8, 256>>>(con1_asrc, con1_adst);
    gat1_warp<<<(NN + 7) / 8, 256>>>();

    // 9-10: BN3 stats (relu fused into read), finalize
    bn_stats<<<BNPART, 256>>>(nullptr, 1);
    bn_finalize<<<1, 256>>>(bn3_g, bn3_b);

    // 11-12: layer 2
    layer2_row<<<(NN + 7) / 8, 256>>>(lin3_W, lin3_b, con3_W, con3_asrc, con3_adst, con3_b, out);
    gat_l2<<<(NN + 7) / 8, 256>>>(out);
}

// round 13
// speedup vs baseline: 1.1685x; 1.1568x over previous
#include <cuda_runtime.h>
#include <cuda_bf16.h>
#include <cstdint>

#define NN 50000
#define EE 800000
#define FDIM 256
#define HEADS 4
#define HID 64
#define BNPART 256

// ---------------- scratch (static device globals; allocation-free) ----------------
__device__ float  d_y1[NN * FDIM];     // linear1 output + GAT1 aggregation -> x1
__device__ float  d_h1[NN * FDIM];     // GAT1 transformed features
__device__ __nv_bfloat16 d_a_hi[NN * FDIM];   // BN(x) in bf16 hi
__device__ __nv_bfloat16 d_a_lo[NN * FDIM];   // residual lo
__device__ __nv_bfloat16 d_w_hi[2 * FDIM * FDIM];  // [mat][n][k] transposed weights
__device__ __nv_bfloat16 d_w_lo[2 * FDIM * FDIM];
__device__ float4 d_als1[NN];
__device__ float4 d_ald1[NN];
__device__ float4 d_p3[NN];            // packed layer-2: (als3, h0, h1, ald3)
__device__ float  d_bnps[BNPART * FDIM];
__device__ float  d_bnpq[BNPART * FDIM];
__device__ float  d_scale[FDIM];
__device__ float  d_shift[FDIM];
__device__ int d_rowptr[NN + 1];
__device__ int d_cursor[NN];
__device__ int d_csr_src[EE];
__device__ int d_chunksum[64];

__device__ __forceinline__ float lrelu(float x) { return x > 0.f ? x : 0.2f * x; }

// ---------------- BN stats: per-block partials (no atomics, no pre-zero) ----------------
__global__ void bn_stats(const float* __restrict__ x, int dorelu) {
    const float* src = x ? x : (const float*)d_y1;
    int c = threadIdx.x;
    float s = 0.f, s2 = 0.f;
    for (int r = blockIdx.x; r < NN; r += BNPART) {
        float v = src[r * FDIM + c];
        if (dorelu) v = fmaxf(v, 0.f);
        s += v; s2 += v * v;
    }
    d_bnps[blockIdx.x * FDIM + c] = s;
    d_bnpq[blockIdx.x * FDIM + c] = s2;
}
__global__ void bn_finalize(const float* __restrict__ g, const float* __restrict__ b) {
    int c = threadIdx.x;
    float s = 0.f, q = 0.f;
    #pragma unroll 8
    for (int i = 0; i < BNPART; i++) {
        s += d_bnps[i * FDIM + c];
        q += d_bnpq[i * FDIM + c];
    }
    const float invn = 1.0f / (float)NN;
    float mu = s * invn;
    float var = q * invn - mu * mu;
    float rs = rsqrtf(var + 1e-5f);
    float sc = rs * g[c];
    d_scale[c] = sc;
    d_shift[c] = b[c] - mu * sc;
}

// ---------------- prep: BN+hi/lo conv of A, weight transpose+conv, rowptr zero ----------------
#define PREP_A 12500
#define PREP_W 512
#define PREP_Z 196
__global__ void prep_k(const float* __restrict__ x,
                       const float* __restrict__ W0, const float* __restrict__ W1) {
    int bid = blockIdx.x;
    int t = threadIdx.x;
    if (bid < PREP_A) {
        int i = bid * 256 + t;
        int c = (i & 63) << 2;
        float4 v = ((const float4*)x)[i];
        float4 sc = *(const float4*)&d_scale[c];
        float4 sh = *(const float4*)&d_shift[c];
        float a0 = v.x * sc.x + sh.x, a1 = v.y * sc.y + sh.y;
        float a2 = v.z * sc.z + sh.z, a3 = v.w * sc.w + sh.w;
        __nv_bfloat16 h0 = __float2bfloat16_rn(a0), h1 = __float2bfloat16_rn(a1);
        __nv_bfloat16 h2 = __float2bfloat16_rn(a2), h3 = __float2bfloat16_rn(a3);
        __nv_bfloat162* ph = (__nv_bfloat162*)d_a_hi;
        ph[i * 2]     = __nv_bfloat162(h0, h1);
        ph[i * 2 + 1] = __nv_bfloat162(h2, h3);
        __nv_bfloat162* pl = (__nv_bfloat162*)d_a_lo;
        pl[i * 2]     = __nv_bfloat162(__float2bfloat16_rn(a0 - __bfloat162float(h0)),
                                       __float2bfloat16_rn(a1 - __bfloat162float(h1)));
        pl[i * 2 + 1] = __nv_bfloat162(__float2bfloat16_rn(a2 - __bfloat162float(h2)),
                                       __float2bfloat16_rn(a3 - __bfloat162float(h3)));
    } else if (bid < PREP_A + PREP_W) {
        int i = (bid - PREP_A) * 256 + t;
        int mat = i >> 16, r = i & 65535;
        int n = r >> 8, k = r & 255;
        const float* W = mat ? W1 : W0;
        float v = W[k * 256 + n];
        __nv_bfloat16 h = __float2bfloat16_rn(v);
        d_w_hi[i] = h;
        d_w_lo[i] = __float2bfloat16_rn(v - __bfloat162float(h));
    } else {
        int i = (bid - PREP_A - PREP_W) * 256 + t;
        if (i <= NN) d_rowptr[i] = 0;
    }
}

// ---------------- CSR build ----------------
__global__ void hist_k(const int* __restrict__ ei) {
    int e = blockIdx.x * blockDim.x + threadIdx.x;
    if (e < EE) atomicAdd(&d_rowptr[ei[EE + e] + 1], 1);
}
__global__ void scan1_k() {
    __shared__ int s[1024];
    int tid = threadIdx.x;
    int i = blockIdx.x * 1024 + tid;
    int v = (i <= NN) ? d_rowptr[i] : 0;
    s[tid] = v;
    __syncthreads();
    #pragma unroll
    for (int off = 1; off < 1024; off <<= 1) {
        int add = (tid >= off) ? s[tid - off] : 0;
        __syncthreads();
        s[tid] += add;
        __syncthreads();
    }
    if (i <= NN) {
        d_rowptr[i] = s[tid];
        if (blockIdx.x == 0 && i < NN) d_cursor[i] = s[tid];  // chunk-0 values are final
    }
    if (tid == 1023) d_chunksum[blockIdx.x] = s[1023];
}
__global__ void scan2_k(int nchunks) {
    __shared__ int s[64];
    int tid = threadIdx.x;
    int v = (tid < nchunks) ? d_chunksum[tid] : 0;
    s[tid] = v;
    __syncthreads();
    #pragma unroll
    for (int off = 1; off < 64; off <<= 1) {
        int add = (tid >= off) ? s[tid - off] : 0;
        __syncthreads();
        s[tid] += add;
        __syncthreads();
    }
    d_chunksum[tid] = s[tid];
}
__global__ void scan3_k() {
    int chunk = blockIdx.x + 1;
    int i = chunk * 1024 + threadIdx.x;
    if (i <= NN) {
        int v = d_rowptr[i] + d_chunksum[chunk - 1];
        d_rowptr[i] = v;
        if (i < NN) d_cursor[i] = v;                          // fused cursor init
    }
}

// ---------------- fused: CSR scatter + layer-1 logit contributions ----------------
// Two independent jobs at this point in the DAG (scatter needs scan; compute_al
// needs only the GEMM) — one grid overlaps atomic-latency work with streaming.
#define SCAT_B 3125                    // (EE+255)/256
#define AL_B 6250                      // (NN+7)/8
__global__ void scatter_al_k(const int* __restrict__ ei,
                             const float* __restrict__ asrc,
                             const float* __restrict__ adst) {
    if (blockIdx.x < SCAT_B) {
        int e = blockIdx.x * 256 + threadIdx.x;
        if (e >= EE) return;
        int s = ei[e], t = ei[EE + e];
        int pos = atomicAdd(&d_cursor[t], 1);
        d_csr_src[pos] = s;
        return;
    }
    int warp = ((blockIdx.x - SCAT_B) * 256 + threadIdx.x) >> 5;
    int lane = threadIdx.x & 31;
    if (warp >= NN) return;
    const float4* hr = (const float4*)&d_h1[(size_t)warp * 256];
    int head = lane >> 3;
    float s = 0.f, d = 0.f;
    #pragma unroll
    for (int q = 0; q < 2; q++) {
        float4 hv = hr[lane * 2 + q];
        int cbase = (lane * 8 + q * 4) & 63;
        const float* as = asrc + head * 64 + cbase;
        const float* ad = adst + head * 64 + cbase;
        s += hv.x * as[0] + hv.y * as[1] + hv.z * as[2] + hv.w * as[3];
        d += hv.x * ad[0] + hv.y * ad[1] + hv.z * ad[2] + hv.w * ad[3];
    }
    #pragma unroll
    for (int off = 4; off > 0; off >>= 1) {
        s += __shfl_down_sync(0xffffffff, s, off);
        d += __shfl_down_sync(0xffffffff, d, off);
    }
    if ((lane & 7) == 0) {
        ((float*)&d_als1[warp])[head] = s;
        ((float*)&d_ald1[warp])[head] = d;
    }
}

// ---------------- bf16 split tensor-core GEMM: 4-stage deep pipeline, BK=16 ----------------
#define SLDA 24
#define PLANE (128 * SLDA * 2)
#define STG (4 * PLANE)
#define GSMEM (4 * STG)

__device__ __forceinline__ void mma16816(float* d, const uint32_t* a, uint32_t b0, uint32_t b1) {
    asm volatile("mma.sync.aligned.m16n8k16.row.col.f32.bf16.bf16.f32 "
                 "{%0,%1,%2,%3}, {%4,%5,%6,%7}, {%8,%9}, {%0,%1,%2,%3};"
                 : "+f"(d[0]), "+f"(d[1]), "+f"(d[2]), "+f"(d[3])
                 : "r"(a[0]), "r"(a[1]), "r"(a[2]), "r"(a[3]), "r"(b0), "r"(b1));
}
__device__ __forceinline__ void ldsm4(uint32_t* r, uint32_t addr) {
    asm volatile("ldmatrix.sync.aligned.m8n8.x4.shared.b16 {%0,%1,%2,%3}, [%4];"
                 : "=r"(r[0]), "=r"(r[1]), "=r"(r[2]), "=r"(r[3]) : "r"(addr));
}
__device__ __forceinline__ void cpa16(uint32_t saddr, const void* gaddr, int bytes) {
    asm volatile("cp.async.cg.shared.global [%0], [%1], 16, %2;"
                 :: "r"(saddr), "l"(gaddr), "r"(bytes));
}

extern __shared__ char dynsmem[];

__global__ void __launch_bounds__(256, 2)
gemm_bf16(const float* __restrict__ b0a, const float* __restrict__ b0b) {
    int t = threadIdx.x;
    int mat = blockIdx.x >> 1;
    int n0 = (blockIdx.x & 1) * 128;
    int m0 = blockIdx.y * 128;
    const __nv_bfloat16* Bh = d_w_hi + mat * 65536;
    const __nv_bfloat16* Bl = d_w_lo + mat * 65536;
    float* C = mat ? d_h1 : d_y1;

    int lrow = t >> 1, seg = t & 1;
    int gm = m0 + lrow;
    bool aok = gm < NN;
    int gmc = aok ? gm : 0;
    int abytes = aok ? 16 : 0;

    const char* gAh = (const char*)(d_a_hi + (size_t)gmc * 256) + seg * 16;
    const char* gAl = (const char*)(d_a_lo + (size_t)gmc * 256) + seg * 16;
    const char* gBh = (const char*)(Bh + (size_t)(n0 + lrow) * 256) + seg * 16;
    const char* gBl = (const char*)(Bl + (size_t)(n0 + lrow) * 256) + seg * 16;

    uint32_t smem0 = (uint32_t)__cvta_generic_to_shared(dynsmem);
    uint32_t rowoff = (uint32_t)(lrow * 48 + seg * 16);

    auto issue = [&](int slab, int buf) {
        uint32_t base = smem0 + buf * STG + rowoff;
        int go = slab * 32;
        cpa16(base,             gAh + go, abytes);
        cpa16(base + PLANE,     gAl + go, abytes);
        cpa16(base + 2 * PLANE, gBh + go, 16);
        cpa16(base + 3 * PLANE, gBl + go, 16);
        asm volatile("cp.async.commit_group;");
    };

    issue(0, 0);
    issue(1, 1);
    issue(2, 2);

    int wid = t >> 5, lane = t & 31;
    int wm0 = (wid & 1) * 64, wn0 = (wid >> 1) * 32;
    float acc[4][4][4] = {};

    int a_r = (lane & 15);
    int a_c = (lane >> 4) << 3;
    int b_r = (lane & 7) + ((lane & 16) ? 8 : 0);
    int b_c = (lane & 8) ? 8 : 0;

    for (int s = 0; s < 16; s++) {
        asm volatile("cp.async.wait_group 2;");
        __syncthreads();
        if (s + 3 < 16) issue(s + 3, (s + 3) & 3);
        else            asm volatile("cp.async.commit_group;");

        uint32_t sAu = smem0 + (s & 3) * STG;
        uint32_t sBu = sAu + 2 * PLANE;
        uint32_t bh[2][4], bl[2][4];
        #pragma unroll
        for (int jp = 0; jp < 2; jp++) {
            uint32_t addr = sBu + (uint32_t)(((wn0 + jp * 16 + b_r) * SLDA + b_c) * 2);
            ldsm4(bh[jp], addr);
            ldsm4(bl[jp], addr + PLANE);
        }
        #pragma unroll
        for (int i = 0; i < 4; i++) {
            uint32_t ah[4], al[4];
            uint32_t addr = sAu + (uint32_t)(((wm0 + i * 16 + a_r) * SLDA + a_c) * 2);
            ldsm4(ah, addr);
            ldsm4(al, addr + PLANE);
            #pragma unroll
            for (int j = 0; j < 4; j++) {
                int jp = j >> 1, o = (j & 1) * 2;
                mma16816(acc[i][j], ah, bh[jp][o], bh[jp][o + 1]);
                mma16816(acc[i][j], ah, bl[jp][o], bl[jp][o + 1]);
                mma16816(acc[i][j], al, bh[jp][o], bh[jp][o + 1]);
            }
        }
    }

    int g = lane >> 2, tq = lane & 3;
    #pragma unroll
    for (int j = 0; j < 4; j++) {
        int gcol = n0 + wn0 + j * 8 + tq * 2;
        float bx = 0.f, by = 0.f;
        if (!mat) {
            bx = b0a[gcol] + b0b[gcol];
            by = b0a[gcol + 1] + b0b[gcol + 1];
        }
        #pragma unroll
        for (int i = 0; i < 4; i++) {
            int r0 = m0 + wm0 + i * 16 + g;
            if (r0 < NN)
                *(float2*)&C[(size_t)r0 * 256 + gcol] =
                    make_float2(acc[i][j][0] + bx, acc[i][j][1] + by);
            int r1 = r0 + 8;
            if (r1 < NN)
                *(float2*)&C[(size_t)r1 * 256 + gcol] =
                    make_float2(acc[i][j][2] + bx, acc[i][j][3] + by);
        }
    }
}

// ---------------- layer-1 GAT: warp/dst, shfl-broadcast of precomputed ex ----------------
__global__ void gat1_warp() {
    int d = (blockIdx.x * blockDim.x + threadIdx.x) >> 5;
    int lane = threadIdx.x & 31;
    if (d >= NN) return;
    int b = d_rowptr[d], e = d_rowptr[d + 1];
    if (b == e) return;
    float4 ald = d_ald1[d];
    int h = lane >> 3;
    int coff = lane * 8;
    float4 acc0 = make_float4(0.f, 0.f, 0.f, 0.f);
    float4 acc1 = make_float4(0.f, 0.f, 0.f, 0.f);
    float den = 0.f;
    const float* __restrict__ hp = (const float*)d_h1;

    for (int c0 = b; c0 < e; c0 += 32) {
        int cnt = min(32, e - c0);
        int src = 0;
        float4 ex = make_float4(0.f, 0.f, 0.f, 0.f);
        if (lane < cnt) {
            src = d_csr_src[c0 + lane];
            float4 a = d_als1[src];
            ex.x = __expf(lrelu(a.x + ald.x));
            ex.y = __expf(lrelu(a.y + ald.y));
            ex.z = __expf(lrelu(a.z + ald.z));
            ex.w = __expf(lrelu(a.w + ald.w));
        }
        #pragma unroll 4
        for (int j = 0; j < cnt; j++) {
            int   sj = __shfl_sync(0xffffffffu, src,  j);
            float e0 = __shfl_sync(0xffffffffu, ex.x, j);
            float e1 = __shfl_sync(0xffffffffu, ex.y, j);
            float e2 = __shfl_sync(0xffffffffu, ex.z, j);
            float e3 = __shfl_sync(0xffffffffu, ex.w, j);
            float w = (h == 0) ? e0 : (h == 1) ? e1 : (h == 2) ? e2 : e3;
            den += w;
            const float4* hv = (const float4*)&hp[(size_t)sj * 256 + coff];
            float4 v0 = hv[0], v1 = hv[1];
            acc0.x += w * v0.x; acc0.y += w * v0.y;
            acc0.z += w * v0.z; acc0.w += w * v0.w;
            acc1.x += w * v1.x; acc1.y += w * v1.y;
            acc1.z += w * v1.z; acc1.w += w * v1.w;
        }
    }
    float r = 1.f / (den + 1e-16f);
    float4* yp = (float4*)&d_y1[(size_t)d * 256 + coff];
    float4 o0 = yp[0], o1 = yp[1];
    o0.x += acc0.x * r; o0.y += acc0.y * r; o0.z += acc0.z * r; o0.w += acc0.w * r;
    o1.x += acc1.x * r; o1.y += acc1.y * r; o1.z += acc1.z * r; o1.w += acc1.w * r;
    yp[0] = o0; yp[1] = o1;
}

// ---------------- layer 2: fused relu+BN + linear3 + GAT2 features/logits ----------------
__global__ void layer2_row(const float* __restrict__ lin3W, const float* __restrict__ lin3b,
                           const float* __restrict__ con3W, const float* __restrict__ asrc,
                           const float* __restrict__ adst, const float* __restrict__ con3b,
                           float* __restrict__ out) {
    int warp = (blockIdx.x * blockDim.x + threadIdx.x) >> 5;
    int lane = threadIdx.x & 31;
    if (warp >= NN) return;
    const float* row = (const float*)d_y1 + (size_t)warp * 256;
    float y0 = 0.f, y1v = 0.f, h0 = 0.f, h1v = 0.f;
    #pragma unroll
    for (int q = 0; q < 8; q++) {
        int c = lane + q * 32;
        float v = fmaxf(row[c], 0.f) * d_scale[c] + d_shift[c];
        y0  += v * lin3W[c * 2];
        y1v += v * lin3W[c * 2 + 1];
        h0  += v * con3W[c * 2];
        h1v += v * con3W[c * 2 + 1];
    }
    #pragma unroll
    for (int off = 16; off > 0; off >>= 1) {
        y0  += __shfl_xor_sync(0xffffffff, y0,  off);
        y1v += __shfl_xor_sync(0xffffffff, y1v, off);
        h0  += __shfl_xor_sync(0xffffffff, h0,  off);
        h1v += __shfl_xor_sync(0xffffffff, h1v, off);
    }
    if (lane == 0) {
        out[warp * 2]     = y0  + lin3b[0] + con3b[0];
        out[warp * 2 + 1] = y1v + lin3b[1] + con3b[1];
        d_p3[warp] = make_float4(h0 * asrc[0] + h1v * asrc[1],
                                 h0, h1v,
                                 h0 * adst[0] + h1v * adst[1]);
    }
}

// ---------------- layer-2 GAT + final relu (warp/dst, single LDG.128 per edge) ----------------
__global__ void gat_l2(float* __restrict__ out) {
    int d = (blockIdx.x * blockDim.x + threadIdx.x) >> 5;
    int lane = threadIdx.x & 31;
    if (d >= NN) return;
    int b = d_rowptr[d], e = d_rowptr[d + 1];
    float ald = d_p3[d].w;
    float den = 0.f, m0 = 0.f, m1 = 0.f;
    for (int j = b + lane; j < e; j += 32) {
        int src = d_csr_src[j];
        float4 p = d_p3[src];
        float ex = __expf(lrelu(p.x + ald));
        den += ex; m0 += ex * p.y; m1 += ex * p.z;
    }
    #pragma unroll
    for (int off = 16; off > 0; off >>= 1) {
        den += __shfl_xor_sync(0xffffffff, den, off);
        m0  += __shfl_xor_sync(0xffffffff, m0,  off);
        m1  += __shfl_xor_sync(0xffffffff, m1,  off);
    }
    if (lane == 0) {
        float r = 1.f / (den + 1e-16f);
        out[d * 2]     = fmaxf(out[d * 2]     + m0 * r, 0.f);
        out[d * 2 + 1] = fmaxf(out[d * 2 + 1] + m1 * r, 0.f);
    }
}

// ---------------- launch ----------------
extern "C" void kernel_launch(void* const* d_in, const int* in_sizes, int n_in,
                              void* d_out, int out_size) {
    const float* x         = (const float*)d_in[0];
    const int*   ei        = (const int*)d_in[1];
    const float* bn1_g     = (const float*)d_in[2];
    const float* bn1_b     = (const float*)d_in[3];
    const float* lin1_W    = (const float*)d_in[4];
    const float* lin1_b    = (const float*)d_in[5];
    const float* con1_W    = (const float*)d_in[6];
    const float* con1_asrc = (const float*)d_in[7];
    const float* con1_adst = (const float*)d_in[8];
    const float* con1_b    = (const float*)d_in[9];
    const float* bn3_g     = (const float*)d_in[10];
    const float* bn3_b     = (const float*)d_in[11];
    const float* lin3_W    = (const float*)d_in[12];
    const float* lin3_b    = (const float*)d_in[13];
    const float* con3_W    = (const float*)d_in[14];
    const float* con3_asrc = (const float*)d_in[15];
    const float* con3_adst = (const float*)d_in[16];
    const float* con3_b    = (const float*)d_in[17];
    float* out = (float*)d_out;

    const int NCHUNK = (NN + 1 + 1023) / 1024;   // 49

    cudaFuncSetAttribute(gemm_bf16, cudaFuncAttributeMaxDynamicSharedMemorySize, GSMEM);

    // 1-3: BN1 stats/finalize, fused prep (bnconv + wtconv + rowptr zero)
    bn_stats<<<BNPART, 256>>>(x, 0);
    bn_finalize<<<1, 256>>>(bn1_g, bn1_b);
    prep_k<<<PREP_A + PREP_W + PREP_Z, 256>>>(x, lin1_W, con1_W);

    // 4 (ncu-profiled slot): the dual GEMM
    gemm_bf16<<<dim3(4, (NN + 127) / 128), 256, GSMEM>>>(lin1_b, con1_b);

    // 5-8: CSR build (3-kernel parallel scan, cursor init fused)
    hist_k<<<(EE + 255) / 256, 256>>>(ei);
    scan1_k<<<NCHUNK, 1024>>>();
    scan2_k<<<1, 64>>>(NCHUNK);
    scan3_k<<<NCHUNK - 1, 1024>>>();

    // 9: fused scatter + layer-1 logit contributions (independent jobs, one grid)
    scatter_al_k<<<SCAT_B + AL_B, 256>>>(ei, con1_asrc, con1_adst);

    // 10: warp-per-dst softmax+aggregate
    gat1_warp<<<(NN + 7) / 8, 256>>>();

    // 11-12: BN3 stats (relu fused into read), finalize
    bn_stats<<<BNPART, 256>>>(nullptr, 1);
    bn_finalize<<<1, 256>>>(bn3_g, bn3_b);

    // 13-14: layer 2
    layer2_row<<<(NN + 7) / 8, 256>>>(lin3_W, lin3_b, con3_W, con3_asrc, con3_adst, con3_b, out);
    gat_l2<<<(NN + 7) / 8, 256>>>(out);
}

// round 14
// speedup vs baseline: 1.2479x; 1.0679x over previous
#include <cuda_runtime.h>
#include <cuda_bf16.h>
#include <cuda_fp16.h>
#include <cstdint>

#define NN 50000
#define EE 800000
#define FDIM 256
#define HEADS 4
#define HID 64
#define BNPART 256

// ---------------- scratch (static device globals; allocation-free) ----------------
__device__ float  d_y1[NN * FDIM];     // linear1 output + GAT1 aggregation -> x1
__device__ __half d_h1h[NN * FDIM];    // GAT1 transformed features (fp16)
__device__ __nv_bfloat16 d_a_hi[NN * FDIM];   // BN(x) in bf16 hi
__device__ __nv_bfloat16 d_a_lo[NN * FDIM];   // residual lo
__device__ __nv_bfloat16 d_w_hi[2 * FDIM * FDIM];  // [mat][n][k] transposed weights
__device__ __nv_bfloat16 d_w_lo[2 * FDIM * FDIM];
__device__ float4 d_als1[NN];
__device__ float4 d_ald1[NN];
__device__ float4 d_p3[NN];            // packed layer-2: (als3, h0, h1, ald3)
__device__ float  d_bnps[BNPART * FDIM];
__device__ float  d_bnpq[BNPART * FDIM];
__device__ float  d_scale[FDIM];
__device__ float  d_shift[FDIM];
__device__ int d_rowptr[NN + 1];
__device__ int d_cursor[NN];
__device__ int d_csr_src[EE];
__device__ int d_chunksum[64];

__device__ __forceinline__ float lrelu(float x) { return x > 0.f ? x : 0.2f * x; }

// ---------------- BN stats: per-block partials (no atomics, no pre-zero) ----------------
__global__ void bn_stats(const float* __restrict__ x, int dorelu) {
    const float* src = x ? x : (const float*)d_y1;
    int c = threadIdx.x;
    float s = 0.f, s2 = 0.f;
    for (int r = blockIdx.x; r < NN; r += BNPART) {
        float v = src[r * FDIM + c];
        if (dorelu) v = fmaxf(v, 0.f);
        s += v; s2 += v * v;
    }
    d_bnps[blockIdx.x * FDIM + c] = s;
    d_bnpq[blockIdx.x * FDIM + c] = s2;
}
__global__ void bn_finalize(const float* __restrict__ g, const float* __restrict__ b) {
    int c = threadIdx.x;
    float s = 0.f, q = 0.f;
    #pragma unroll 8
    for (int i = 0; i < BNPART; i++) {
        s += d_bnps[i * FDIM + c];
        q += d_bnpq[i * FDIM + c];
    }
    const float invn = 1.0f / (float)NN;
    float mu = s * invn;
    float var = q * invn - mu * mu;
    float rs = rsqrtf(var + 1e-5f);
    float sc = rs * g[c];
    d_scale[c] = sc;
    d_shift[c] = b[c] - mu * sc;
}

// ---------------- prep: BN+hi/lo conv of A, weight transpose+conv, rowptr zero ----------------
#define PREP_A 12500
#define PREP_W 512
#define PREP_Z 196
__global__ void prep_k(const float* __restrict__ x,
                       const float* __restrict__ W0, const float* __restrict__ W1) {
    int bid = blockIdx.x;
    int t = threadIdx.x;
    if (bid < PREP_A) {
        int i = bid * 256 + t;
        int c = (i & 63) << 2;
        float4 v = ((const float4*)x)[i];
        float4 sc = *(const float4*)&d_scale[c];
        float4 sh = *(const float4*)&d_shift[c];
        float a0 = v.x * sc.x + sh.x, a1 = v.y * sc.y + sh.y;
        float a2 = v.z * sc.z + sh.z, a3 = v.w * sc.w + sh.w;
        __nv_bfloat16 h0 = __float2bfloat16_rn(a0), h1 = __float2bfloat16_rn(a1);
        __nv_bfloat16 h2 = __float2bfloat16_rn(a2), h3 = __float2bfloat16_rn(a3);
        __nv_bfloat162* ph = (__nv_bfloat162*)d_a_hi;
        ph[i * 2]     = __nv_bfloat162(h0, h1);
        ph[i * 2 + 1] = __nv_bfloat162(h2, h3);
        __nv_bfloat162* pl = (__nv_bfloat162*)d_a_lo;
        pl[i * 2]     = __nv_bfloat162(__float2bfloat16_rn(a0 - __bfloat162float(h0)),
                                       __float2bfloat16_rn(a1 - __bfloat162float(h1)));
        pl[i * 2 + 1] = __nv_bfloat162(__float2bfloat16_rn(a2 - __bfloat162float(h2)),
                                       __float2bfloat16_rn(a3 - __bfloat162float(h3)));
    } else if (bid < PREP_A + PREP_W) {
        int i = (bid - PREP_A) * 256 + t;
        int mat = i >> 16, r = i & 65535;
        int n = r >> 8, k = r & 255;
        const float* W = mat ? W1 : W0;
        float v = W[k * 256 + n];
        __nv_bfloat16 h = __float2bfloat16_rn(v);
        d_w_hi[i] = h;
        d_w_lo[i] = __float2bfloat16_rn(v - __bfloat162float(h));
    } else {
        int i = (bid - PREP_A - PREP_W) * 256 + t;
        if (i <= NN) d_rowptr[i] = 0;
    }
}

// ---------------- CSR build ----------------
__global__ void hist_k(const int* __restrict__ ei) {
    int e = blockIdx.x * blockDim.x + threadIdx.x;
    if (e < EE) atomicAdd(&d_rowptr[ei[EE + e] + 1], 1);
}
__global__ void scan1_k() {
    __shared__ int s[1024];
    int tid = threadIdx.x;
    int i = blockIdx.x * 1024 + tid;
    int v = (i <= NN) ? d_rowptr[i] : 0;
    s[tid] = v;
    __syncthreads();
    #pragma unroll
    for (int off = 1; off < 1024; off <<= 1) {
        int add = (tid >= off) ? s[tid - off] : 0;
        __syncthreads();
        s[tid] += add;
        __syncthreads();
    }
    if (i <= NN) {
        d_rowptr[i] = s[tid];
        if (blockIdx.x == 0 && i < NN) d_cursor[i] = s[tid];
    }
    if (tid == 1023) d_chunksum[blockIdx.x] = s[1023];
}
__global__ void scan2_k(int nchunks) {
    __shared__ int s[64];
    int tid = threadIdx.x;
    int v = (tid < nchunks) ? d_chunksum[tid] : 0;
    s[tid] = v;
    __syncthreads();
    #pragma unroll
    for (int off = 1; off < 64; off <<= 1) {
        int add = (tid >= off) ? s[tid - off] : 0;
        __syncthreads();
        s[tid] += add;
        __syncthreads();
    }
    d_chunksum[tid] = s[tid];
}
__global__ void scan3_k() {
    int chunk = blockIdx.x + 1;
    int i = chunk * 1024 + threadIdx.x;
    if (i <= NN) {
        int v = d_rowptr[i] + d_chunksum[chunk - 1];
        d_rowptr[i] = v;
        if (i < NN) d_cursor[i] = v;
    }
}

// ---------------- fused: CSR scatter + layer-1 logit contributions (fp16 h1) ----------------
#define SCAT_B 3125                    // (EE+255)/256
#define AL_B 6250                      // (NN+7)/8
__global__ void scatter_al_k(const int* __restrict__ ei,
                             const float* __restrict__ asrc,
                             const float* __restrict__ adst) {
    if (blockIdx.x < SCAT_B) {
        int e = blockIdx.x * 256 + threadIdx.x;
        if (e >= EE) return;
        int s = ei[e], t = ei[EE + e];
        int pos = atomicAdd(&d_cursor[t], 1);
        d_csr_src[pos] = s;
        return;
    }
    int warp = ((blockIdx.x - SCAT_B) * 256 + threadIdx.x) >> 5;
    int lane = threadIdx.x & 31;
    if (warp >= NN) return;
    int head = lane >> 3;
    int coff = lane * 8;
    // 8 halves = 16B aligned load
    uint4 raw = *(const uint4*)&d_h1h[(size_t)warp * 256 + coff];
    __half2 p0 = *(__half2*)&raw.x, p1 = *(__half2*)&raw.y;
    __half2 p2 = *(__half2*)&raw.z, p3 = *(__half2*)&raw.w;
    float2 f0 = __half22float2(p0), f1 = __half22float2(p1);
    float2 f2 = __half22float2(p2), f3 = __half22float2(p3);
    int cbase = coff & 63;
    const float* as = asrc + head * 64 + cbase;
    const float* ad = adst + head * 64 + cbase;
    float s = f0.x*as[0] + f0.y*as[1] + f1.x*as[2] + f1.y*as[3]
            + f2.x*as[4] + f2.y*as[5] + f3.x*as[6] + f3.y*as[7];
    float d = f0.x*ad[0] + f0.y*ad[1] + f1.x*ad[2] + f1.y*ad[3]
            + f2.x*ad[4] + f2.y*ad[5] + f3.x*ad[6] + f3.y*ad[7];
    #pragma unroll
    for (int off = 4; off > 0; off >>= 1) {
        s += __shfl_down_sync(0xffffffff, s, off);
        d += __shfl_down_sync(0xffffffff, d, off);
    }
    if ((lane & 7) == 0) {
        ((float*)&d_als1[warp])[head] = s;
        ((float*)&d_ald1[warp])[head] = d;
    }
}

// ---------------- bf16 split tensor-core GEMM: 4-stage deep pipeline, BK=16 ----------------
#define SLDA 24
#define PLANE (128 * SLDA * 2)
#define STG (4 * PLANE)
#define GSMEM (4 * STG)

__device__ __forceinline__ void mma16816(float* d, const uint32_t* a, uint32_t b0, uint32_t b1) {
    asm volatile("mma.sync.aligned.m16n8k16.row.col.f32.bf16.bf16.f32 "
                 "{%0,%1,%2,%3}, {%4,%5,%6,%7}, {%8,%9}, {%0,%1,%2,%3};"
                 : "+f"(d[0]), "+f"(d[1]), "+f"(d[2]), "+f"(d[3])
                 : "r"(a[0]), "r"(a[1]), "r"(a[2]), "r"(a[3]), "r"(b0), "r"(b1));
}
__device__ __forceinline__ void ldsm4(uint32_t* r, uint32_t addr) {
    asm volatile("ldmatrix.sync.aligned.m8n8.x4.shared.b16 {%0,%1,%2,%3}, [%4];"
                 : "=r"(r[0]), "=r"(r[1]), "=r"(r[2]), "=r"(r[3]) : "r"(addr));
}
__device__ __forceinline__ void cpa16(uint32_t saddr, const void* gaddr, int bytes) {
    asm volatile("cp.async.cg.shared.global [%0], [%1], 16, %2;"
                 :: "r"(saddr), "l"(gaddr), "r"(bytes));
}

extern __shared__ char dynsmem[];

__global__ void __launch_bounds__(256, 2)
gemm_bf16(const float* __restrict__ b0a, const float* __restrict__ b0b) {
    int t = threadIdx.x;
    int mat = blockIdx.x >> 1;
    int n0 = (blockIdx.x & 1) * 128;
    int m0 = blockIdx.y * 128;
    const __nv_bfloat16* Bh = d_w_hi + mat * 65536;
    const __nv_bfloat16* Bl = d_w_lo + mat * 65536;

    int lrow = t >> 1, seg = t & 1;
    int gm = m0 + lrow;
    bool aok = gm < NN;
    int gmc = aok ? gm : 0;
    int abytes = aok ? 16 : 0;

    const char* gAh = (const char*)(d_a_hi + (size_t)gmc * 256) + seg * 16;
    const char* gAl = (const char*)(d_a_lo + (size_t)gmc * 256) + seg * 16;
    const char* gBh = (const char*)(Bh + (size_t)(n0 + lrow) * 256) + seg * 16;
    const char* gBl = (const char*)(Bl + (size_t)(n0 + lrow) * 256) + seg * 16;

    uint32_t smem0 = (uint32_t)__cvta_generic_to_shared(dynsmem);
    uint32_t rowoff = (uint32_t)(lrow * 48 + seg * 16);

    auto issue = [&](int slab, int buf) {
        uint32_t base = smem0 + buf * STG + rowoff;
        int go = slab * 32;
        cpa16(base,             gAh + go, abytes);
        cpa16(base + PLANE,     gAl + go, abytes);
        cpa16(base + 2 * PLANE, gBh + go, 16);
        cpa16(base + 3 * PLANE, gBl + go, 16);
        asm volatile("cp.async.commit_group;");
    };

    issue(0, 0);
    issue(1, 1);
    issue(2, 2);

    int wid = t >> 5, lane = t & 31;
    int wm0 = (wid & 1) * 64, wn0 = (wid >> 1) * 32;
    float acc[4][4][4] = {};

    int a_r = (lane & 15);
    int a_c = (lane >> 4) << 3;
    int b_r = (lane & 7) + ((lane & 16) ? 8 : 0);
    int b_c = (lane & 8) ? 8 : 0;

    for (int s = 0; s < 16; s++) {
        asm volatile("cp.async.wait_group 2;");
        __syncthreads();
        if (s + 3 < 16) issue(s + 3, (s + 3) & 3);
        else            asm volatile("cp.async.commit_group;");

        uint32_t sAu = smem0 + (s & 3) * STG;
        uint32_t sBu = sAu + 2 * PLANE;
        uint32_t bh[2][4], bl[2][4];
        #pragma unroll
        for (int jp = 0; jp < 2; jp++) {
            uint32_t addr = sBu + (uint32_t)(((wn0 + jp * 16 + b_r) * SLDA + b_c) * 2);
            ldsm4(bh[jp], addr);
            ldsm4(bl[jp], addr + PLANE);
        }
        #pragma unroll
        for (int i = 0; i < 4; i++) {
            uint32_t ah[4], al[4];
            uint32_t addr = sAu + (uint32_t)(((wm0 + i * 16 + a_r) * SLDA + a_c) * 2);
            ldsm4(ah, addr);
            ldsm4(al, addr + PLANE);
            #pragma unroll
            for (int j = 0; j < 4; j++) {
                int jp = j >> 1, o = (j & 1) * 2;
                mma16816(acc[i][j], ah, bh[jp][o], bh[jp][o + 1]);
                mma16816(acc[i][j], ah, bl[jp][o], bl[jp][o + 1]);
                mma16816(acc[i][j], al, bh[jp][o], bh[jp][o + 1]);
            }
        }
    }

    int g = lane >> 2, tq = lane & 3;
    if (!mat) {
        float* C = (float*)d_y1;
        #pragma unroll
        for (int j = 0; j < 4; j++) {
            int gcol = n0 + wn0 + j * 8 + tq * 2;
            float bx = b0a[gcol] + b0b[gcol];
            float by = b0a[gcol + 1] + b0b[gcol + 1];
            #pragma unroll
            for (int i = 0; i < 4; i++) {
                int r0 = m0 + wm0 + i * 16 + g;
                if (r0 < NN)
                    *(float2*)&C[(size_t)r0 * 256 + gcol] =
                        make_float2(acc[i][j][0] + bx, acc[i][j][1] + by);
                int r1 = r0 + 8;
                if (r1 < NN)
                    *(float2*)&C[(size_t)r1 * 256 + gcol] =
                        make_float2(acc[i][j][2] + bx, acc[i][j][3] + by);
            }
        }
    } else {
        __half* C = (__half*)d_h1h;
        #pragma unroll
        for (int j = 0; j < 4; j++) {
            int gcol = n0 + wn0 + j * 8 + tq * 2;
            #pragma unroll
            for (int i = 0; i < 4; i++) {
                int r0 = m0 + wm0 + i * 16 + g;
                if (r0 < NN)
                    *(__half2*)&C[(size_t)r0 * 256 + gcol] =
                        __floats2half2_rn(acc[i][j][0], acc[i][j][1]);
                int r1 = r0 + 8;
                if (r1 < NN)
                    *(__half2*)&C[(size_t)r1 * 256 + gcol] =
                        __floats2half2_rn(acc[i][j][2], acc[i][j][3]);
            }
        }
    }
}

// ---------------- layer-1 GAT: warp/dst, shfl-broadcast of precomputed ex, fp16 gather ----------------
__global__ void gat1_warp() {
    int d = (blockIdx.x * blockDim.x + threadIdx.x) >> 5;
    int lane = threadIdx.x & 31;
    if (d >= NN) return;
    int b = d_rowptr[d], e = d_rowptr[d + 1];
    if (b == e) return;
    float4 ald = d_ald1[d];
    int h = lane >> 3;
    int coff = lane * 8;
    float4 acc0 = make_float4(0.f, 0.f, 0.f, 0.f);
    float4 acc1 = make_float4(0.f, 0.f, 0.f, 0.f);
    float den = 0.f;
    const __half* __restrict__ hp = (const __half*)d_h1h;

    for (int c0 = b; c0 < e; c0 += 32) {
        int cnt = min(32, e - c0);
        int src = 0;
        float4 ex = make_float4(0.f, 0.f, 0.f, 0.f);
        if (lane < cnt) {
            src = d_csr_src[c0 + lane];
            float4 a = d_als1[src];
            ex.x = __expf(lrelu(a.x + ald.x));
            ex.y = __expf(lrelu(a.y + ald.y));
            ex.z = __expf(lrelu(a.z + ald.z));
            ex.w = __expf(lrelu(a.w + ald.w));
        }
        #pragma unroll 4
        for (int j = 0; j < cnt; j++) {
            int   sj = __shfl_sync(0xffffffffu, src,  j);
            float e0 = __shfl_sync(0xffffffffu, ex.x, j);
            float e1 = __shfl_sync(0xffffffffu, ex.y, j);
            float e2 = __shfl_sync(0xffffffffu, ex.z, j);
            float e3 = __shfl_sync(0xffffffffu, ex.w, j);
            float w = (h == 0) ? e0 : (h == 1) ? e1 : (h == 2) ? e2 : e3;
            den += w;
            uint4 raw = *(const uint4*)&hp[(size_t)sj * 256 + coff];
            float2 f0 = __half22float2(*(__half2*)&raw.x);
            float2 f1 = __half22float2(*(__half2*)&raw.y);
            float2 f2 = __half22float2(*(__half2*)&raw.z);
            float2 f3 = __half22float2(*(__half2*)&raw.w);
            acc0.x += w * f0.x; acc0.y += w * f0.y;
            acc0.z += w * f1.x; acc0.w += w * f1.y;
            acc1.x += w * f2.x; acc1.y += w * f2.y;
            acc1.z += w * f3.x; acc1.w += w * f3.y;
        }
    }
    float r = 1.f / (den + 1e-16f);
    float4* yp = (float4*)&d_y1[(size_t)d * 256 + coff];
    float4 o0 = yp[0], o1 = yp[1];
    o0.x += acc0.x * r; o0.y += acc0.y * r; o0.z += acc0.z * r; o0.w += acc0.w * r;
    o1.x += acc1.x * r; o1.y += acc1.y * r; o1.z += acc1.z * r; o1.w += acc1.w * r;
    yp[0] = o0; yp[1] = o1;
}

// ---------------- layer 2: fused relu+BN + linear3 + GAT2 features/logits ----------------
__global__ void layer2_row(const float* __restrict__ lin3W, const float* __restrict__ lin3b,
                           const float* __restrict__ con3W, const float* __restrict__ asrc,
                           const float* __restrict__ adst, const float* __restrict__ con3b,
                           float* __restrict__ out) {
    int warp = (blockIdx.x * blockDim.x + threadIdx.x) >> 5;
    int lane = threadIdx.x & 31;
    if (warp >= NN) return;
    const float* row = (const float*)d_y1 + (size_t)warp * 256;
    float y0 = 0.f, y1v = 0.f, h0 = 0.f, h1v = 0.f;
    #pragma unroll
    for (int q = 0; q < 8; q++) {
        int c = lane + q * 32;
        float v = fmaxf(row[c], 0.f) * d_scale[c] + d_shift[c];
        y0  += v * lin3W[c * 2];
        y1v += v * lin3W[c * 2 + 1];
        h0  += v * con3W[c * 2];
        h1v += v * con3W[c * 2 + 1];
    }
    #pragma unroll
    for (int off = 16; off > 0; off >>= 1) {
        y0  += __shfl_xor_sync(0xffffffff, y0,  off);
        y1v += __shfl_xor_sync(0xffffffff, y1v, off);
        h0  += __shfl_xor_sync(0xffffffff, h0,  off);
        h1v += __shfl_xor_sync(0xffffffff, h1v, off);
    }
    if (lane == 0) {
        out[warp * 2]     = y0  + lin3b[0] + con3b[0];
        out[warp * 2 + 1] = y1v + lin3b[1] + con3b[1];
        d_p3[warp] = make_float4(h0 * asrc[0] + h1v * asrc[1],
                                 h0, h1v,
                                 h0 * adst[0] + h1v * adst[1]);
    }
}

// ---------------- layer-2 GAT + final relu (warp/dst, single LDG.128 per edge) ----------------
__global__ void gat_l2(float* __restrict__ out) {
    int d = (blockIdx.x * blockDim.x + threadIdx.x) >> 5;
    int lane = threadIdx.x & 31;
    if (d >= NN) return;
    int b = d_rowptr[d], e = d_rowptr[d + 1];
    float ald = d_p3[d].w;
    float den = 0.f, m0 = 0.f, m1 = 0.f;
    for (int j = b + lane; j < e; j += 32) {
        int src = d_csr_src[j];
        float4 p = d_p3[src];
        float ex = __expf(lrelu(p.x + ald));
        den += ex; m0 += ex * p.y; m1 += ex * p.z;
    }
    #pragma unroll
    for (int off = 16; off > 0; off >>= 1) {
        den += __shfl_xor_sync(0xffffffff, den, off);
        m0  += __shfl_xor_sync(0xffffffff, m0,  off);
        m1  += __shfl_xor_sync(0xffffffff, m1,  off);
    }
    if (lane == 0) {
        float r = 1.f / (den + 1e-16f);
        out[d * 2]     = fmaxf(out[d * 2]     + m0 * r, 0.f);
        out[d * 2 + 1] = fmaxf(out[d * 2 + 1] + m1 * r, 0.f);
    }
}

// ---------------- launch ----------------
extern "C" void kernel_launch(void* const* d_in, const int* in_sizes, int n_in,
                              void* d_out, int out_size) {
    const float* x         = (const float*)d_in[0];
    const int*   ei        = (const int*)d_in[1];
    const float* bn1_g     = (const float*)d_in[2];
    const float* bn1_b     = (const float*)d_in[3];
    const float* lin1_W    = (const float*)d_in[4];
    const float* lin1_b    = (const float*)d_in[5];
    const float* con1_W    = (const float*)d_in[6];
    const float* con1_asrc = (const float*)d_in[7];
    const float* con1_adst = (const float*)d_in[8];
    const float* con1_b    = (const float*)d_in[9];
    const float* bn3_g     = (const float*)d_in[10];
    const float* bn3_b     = (const float*)d_in[11];
    const float* lin3_W    = (const float*)d_in[12];
    const float* lin3_b    = (const float*)d_in[13];
    const float* con3_W    = (const float*)d_in[14];
    const float* con3_asrc = (const float*)d_in[15];
    const float* con3_adst = (const float*)d_in[16];
    const float* con3_b    = (const float*)d_in[17];
    float* out = (float*)d_out;

    const int NCHUNK = (NN + 1 + 1023) / 1024;   // 49

    cudaFuncSetAttribute(gemm_bf16, cudaFuncAttributeMaxDynamicSharedMemorySize, GSMEM);

    // 1-3: BN1 stats/finalize, fused prep (bnconv + wtconv + rowptr zero)
    bn_stats<<<BNPART, 256>>>(x, 0);
    bn_finalize<<<1, 256>>>(bn1_g, bn1_b);
    prep_k<<<PREP_A + PREP_W + PREP_Z, 256>>>(x, lin1_W, con1_W);

    // 4 (ncu-profiled slot): the dual GEMM (h1 output in fp16)
    gemm_bf16<<<dim3(4, (NN + 127) / 128), 256, GSMEM>>>(lin1_b, con1_b);

    // 5-8: CSR build (3-kernel parallel scan, cursor init fused)
    hist_k<<<(EE + 255) / 256, 256>>>(ei);
    scan1_k<<<NCHUNK, 1024>>>();
    scan2_k<<<1, 64>>>(NCHUNK);
    scan3_k<<<NCHUNK - 1, 1024>>>();

    // 9: fused scatter + layer-1 logit contributions
    scatter_al_k<<<SCAT_B + AL_B, 256>>>(ei, con1_asrc, con1_adst);

    // 10: warp-per-dst softmax+aggregate (fp16 gather)
    gat1_warp<<<(NN + 7) / 8, 256>>>();

    // 11-12: BN3 stats (relu fused into read), finalize
    bn_stats<<<BNPART, 256>>>(nullptr, 1);
    bn_finalize<<<1, 256>>>(bn3_g, bn3_b);

    // 13-14: layer 2
    layer2_row<<<(NN + 7) / 8, 256>>>(lin3_W, lin3_b, con3_W, con3_asrc, con3_adst, con3_b, out);
    gat_l2<<<(NN + 7) / 8, 256>>>(out);
}

// round 15
// speedup vs baseline: 1.2688x; 1.0168x over previous
#include <cuda_runtime.h>
#include <cuda_bf16.h>
#include <cuda_fp16.h>
#include <cstdint>

#define NN 50000
#define EE 800000
#define FDIM 256
#define HEADS 4
#define HID 64
#define BNPART 256
#define MTILES 391                     // (NN+127)/128
#define HISTROWS 782                   // ceil(EE/(4*256))

// ---------------- scratch (static device globals; allocation-free) ----------------
__device__ float  d_y1[NN * FDIM];     // linear1 output + GAT1 aggregation -> x1
__device__ __half d_h1h[NN * FDIM];    // GAT1 transformed features (fp16)
__device__ __nv_bfloat16 d_a_hi[NN * FDIM];   // BN(x) in bf16 hi
__device__ __nv_bfloat16 d_a_lo[NN * FDIM];   // residual lo
__device__ __nv_bfloat16 d_w_hi[2 * FDIM * FDIM];  // [mat][n][k] transposed weights
__device__ __nv_bfloat16 d_w_lo[2 * FDIM * FDIM];
__device__ float4 d_als1[NN];
__device__ float4 d_ald1[NN];
__device__ float4 d_p3[NN];            // packed layer-2: (als3, h0, h1, ald3)
__device__ float  d_bnps[BNPART * FDIM];
__device__ float  d_bnpq[BNPART * FDIM];
__device__ float  d_scale[FDIM];
__device__ float  d_shift[FDIM];
__device__ int d_rowptr[NN + 1];
__device__ int d_cursor[NN];
__device__ int d_csr_src[EE];
__device__ int d_chunksum[64];

__device__ __forceinline__ float lrelu(float x) { return x > 0.f ? x : 0.2f * x; }

// ---------------- BN stats: per-block partials (no atomics, no pre-zero) ----------------
__global__ void bn_stats(const float* __restrict__ x, int dorelu) {
    const float* src = x ? x : (const float*)d_y1;
    int c = threadIdx.x;
    float s = 0.f, s2 = 0.f;
    for (int r = blockIdx.x; r < NN; r += BNPART) {
        float v = src[r * FDIM + c];
        if (dorelu) v = fmaxf(v, 0.f);
        s += v; s2 += v * v;
    }
    d_bnps[blockIdx.x * FDIM + c] = s;
    d_bnpq[blockIdx.x * FDIM + c] = s2;
}
__global__ void bn_finalize(const float* __restrict__ g, const float* __restrict__ b) {
    int c = threadIdx.x;
    float s = 0.f, q = 0.f;
    #pragma unroll 8
    for (int i = 0; i < BNPART; i++) {
        s += d_bnps[i * FDIM + c];
        q += d_bnpq[i * FDIM + c];
    }
    const float invn = 1.0f / (float)NN;
    float mu = s * invn;
    float var = q * invn - mu * mu;
    float rs = rsqrtf(var + 1e-5f);
    float sc = rs * g[c];
    d_scale[c] = sc;
    d_shift[c] = b[c] - mu * sc;
}

// ---------------- prep: BN+hi/lo conv of A, weight transpose+conv, rowptr zero ----------------
#define PREP_A 12500
#define PREP_W 512
#define PREP_Z 196
__global__ void prep_k(const float* __restrict__ x,
                       const float* __restrict__ W0, const float* __restrict__ W1) {
    int bid = blockIdx.x;
    int t = threadIdx.x;
    if (bid < PREP_A) {
        int i = bid * 256 + t;
        int c = (i & 63) << 2;
        float4 v = ((const float4*)x)[i];
        float4 sc = *(const float4*)&d_scale[c];
        float4 sh = *(const float4*)&d_shift[c];
        float a0 = v.x * sc.x + sh.x, a1 = v.y * sc.y + sh.y;
        float a2 = v.z * sc.z + sh.z, a3 = v.w * sc.w + sh.w;
        __nv_bfloat16 h0 = __float2bfloat16_rn(a0), h1 = __float2bfloat16_rn(a1);
        __nv_bfloat16 h2 = __float2bfloat16_rn(a2), h3 = __float2bfloat16_rn(a3);
        __nv_bfloat162* ph = (__nv_bfloat162*)d_a_hi;
        ph[i * 2]     = __nv_bfloat162(h0, h1);
        ph[i * 2 + 1] = __nv_bfloat162(h2, h3);
        __nv_bfloat162* pl = (__nv_bfloat162*)d_a_lo;
        pl[i * 2]     = __nv_bfloat162(__float2bfloat16_rn(a0 - __bfloat162float(h0)),
                                       __float2bfloat16_rn(a1 - __bfloat162float(h1)));
        pl[i * 2 + 1] = __nv_bfloat162(__float2bfloat16_rn(a2 - __bfloat162float(h2)),
                                       __float2bfloat16_rn(a3 - __bfloat162float(h3)));
    } else if (bid < PREP_A + PREP_W) {
        int i = (bid - PREP_A) * 256 + t;
        int mat = i >> 16, r = i & 65535;
        int n = r >> 8, k = r & 255;
        const float* W = mat ? W1 : W0;
        float v = W[k * 256 + n];
        __nv_bfloat16 h = __float2bfloat16_rn(v);
        d_w_hi[i] = h;
        d_w_lo[i] = __float2bfloat16_rn(v - __bfloat162float(h));
    } else {
        int i = (bid - PREP_A - PREP_W) * 256 + t;
        if (i <= NN) d_rowptr[i] = 0;
    }
}

// ---------------- CSR scan (scan2 folded into scan3) ----------------
__global__ void scan1_k() {
    __shared__ int s[1024];
    int tid = threadIdx.x;
    int i = blockIdx.x * 1024 + tid;
    int v = (i <= NN) ? d_rowptr[i] : 0;
    s[tid] = v;
    __syncthreads();
    #pragma unroll
    for (int off = 1; off < 1024; off <<= 1) {
        int add = (tid >= off) ? s[tid - off] : 0;
        __syncthreads();
        s[tid] += add;
        __syncthreads();
    }
    if (i <= NN) {
        d_rowptr[i] = s[tid];
        if (blockIdx.x == 0 && i < NN) d_cursor[i] = s[tid];
    }
    if (tid == 1023) d_chunksum[blockIdx.x] = s[1023];
}
__global__ void scan3_k() {
    int chunk = blockIdx.x + 1;
    int base = 0;
    for (int j = 0; j < chunk; j++) base += d_chunksum[j];   // uniform cached loads
    int i = chunk * 1024 + threadIdx.x;
    if (i <= NN) {
        int v = d_rowptr[i] + base;
        d_rowptr[i] = v;
        if (i < NN) d_cursor[i] = v;
    }
}

// ---------------- fused: CSR scatter + layer-1 logit contributions (fp16 h1) ----------------
#define SCAT_B 3125                    // (EE+255)/256
#define AL_B 6250                      // (NN+7)/8
__global__ void scatter_al_k(const int* __restrict__ ei,
                             const float* __restrict__ asrc,
                             const float* __restrict__ adst) {
    if (blockIdx.x < SCAT_B) {
        int e = blockIdx.x * 256 + threadIdx.x;
        if (e >= EE) return;
        int s = ei[e], t = ei[EE + e];
        int pos = atomicAdd(&d_cursor[t], 1);
        d_csr_src[pos] = s;
        return;
    }
    int warp = ((blockIdx.x - SCAT_B) * 256 + threadIdx.x) >> 5;
    int lane = threadIdx.x & 31;
    if (warp >= NN) return;
    int head = lane >> 3;
    int coff = lane * 8;
    uint4 raw = *(const uint4*)&d_h1h[(size_t)warp * 256 + coff];
    __half2 p0 = *(__half2*)&raw.x, p1 = *(__half2*)&raw.y;
    __half2 p2 = *(__half2*)&raw.z, p3 = *(__half2*)&raw.w;
    float2 f0 = __half22float2(p0), f1 = __half22float2(p1);
    float2 f2 = __half22float2(p2), f3 = __half22float2(p3);
    int cbase = coff & 63;
    const float* as = asrc + head * 64 + cbase;
    const float* ad = adst + head * 64 + cbase;
    float s = f0.x*as[0] + f0.y*as[1] + f1.x*as[2] + f1.y*as[3]
            + f2.x*as[4] + f2.y*as[5] + f3.x*as[6] + f3.y*as[7];
    float d = f0.x*ad[0] + f0.y*ad[1] + f1.x*ad[2] + f1.y*ad[3]
            + f2.x*ad[4] + f2.y*ad[5] + f3.x*ad[6] + f3.y*ad[7];
    #pragma unroll
    for (int off = 4; off > 0; off >>= 1) {
        s += __shfl_down_sync(0xffffffff, s, off);
        d += __shfl_down_sync(0xffffffff, d, off);
    }
    if ((lane & 7) == 0) {
        ((float*)&d_als1[warp])[head] = s;
        ((float*)&d_ald1[warp])[head] = d;
    }
}

// ---------------- bf16 split tensor-core GEMM (+ edge histogram tail blocks) ----------------
#define SLDA 24
#define PLANE (128 * SLDA * 2)
#define STG (4 * PLANE)
#define GSMEM (4 * STG)

__device__ __forceinline__ void mma16816(float* d, const uint32_t* a, uint32_t b0, uint32_t b1) {
    asm volatile("mma.sync.aligned.m16n8k16.row.col.f32.bf16.bf16.f32 "
                 "{%0,%1,%2,%3}, {%4,%5,%6,%7}, {%8,%9}, {%0,%1,%2,%3};"
                 : "+f"(d[0]), "+f"(d[1]), "+f"(d[2]), "+f"(d[3])
                 : "r"(a[0]), "r"(a[1]), "r"(a[2]), "r"(a[3]), "r"(b0), "r"(b1));
}
__device__ __forceinline__ void ldsm4(uint32_t* r, uint32_t addr) {
    asm volatile("ldmatrix.sync.aligned.m8n8.x4.shared.b16 {%0,%1,%2,%3}, [%4];"
                 : "=r"(r[0]), "=r"(r[1]), "=r"(r[2]), "=r"(r[3]) : "r"(addr));
}
__device__ __forceinline__ void cpa16(uint32_t saddr, const void* gaddr, int bytes) {
    asm volatile("cp.async.cg.shared.global [%0], [%1], 16, %2;"
                 :: "r"(saddr), "l"(gaddr), "r"(bytes));
}

extern __shared__ char dynsmem[];

__global__ void __launch_bounds__(256, 2)
gemm_bf16(const float* __restrict__ b0a, const float* __restrict__ b0b,
          const int* __restrict__ ei) {
    int t = threadIdx.x;

    // ---- histogram tail blocks (independent work riding the GEMM launch) ----
    if (blockIdx.y >= MTILES) {
        int idx = (blockIdx.y - MTILES) * 4 + blockIdx.x;
        int e = idx * 256 + t;
        if (e < EE) atomicAdd(&d_rowptr[ei[EE + e] + 1], 1);
        return;
    }

    int mat = blockIdx.x >> 1;
    int n0 = (blockIdx.x & 1) * 128;
    int m0 = blockIdx.y * 128;
    const __nv_bfloat16* Bh = d_w_hi + mat * 65536;
    const __nv_bfloat16* Bl = d_w_lo + mat * 65536;

    int lrow = t >> 1, seg = t & 1;
    int gm = m0 + lrow;
    bool aok = gm < NN;
    int gmc = aok ? gm : 0;
    int abytes = aok ? 16 : 0;

    const char* gAh = (const char*)(d_a_hi + (size_t)gmc * 256) + seg * 16;
    const char* gAl = (const char*)(d_a_lo + (size_t)gmc * 256) + seg * 16;
    const char* gBh = (const char*)(Bh + (size_t)(n0 + lrow) * 256) + seg * 16;
    const char* gBl = (const char*)(Bl + (size_t)(n0 + lrow) * 256) + seg * 16;

    uint32_t smem0 = (uint32_t)__cvta_generic_to_shared(dynsmem);
    uint32_t rowoff = (uint32_t)(lrow * 48 + seg * 16);

    auto issue = [&](int slab, int buf) {
        uint32_t base = smem0 + buf * STG + rowoff;
        int go = slab * 32;
        cpa16(base,             gAh + go, abytes);
        cpa16(base + PLANE,     gAl + go, abytes);
        cpa16(base + 2 * PLANE, gBh + go, 16);
        cpa16(base + 3 * PLANE, gBl + go, 16);
        asm volatile("cp.async.commit_group;");
    };

    issue(0, 0);
    issue(1, 1);
    issue(2, 2);

    int wid = t >> 5, lane = t & 31;
    int wm0 = (wid & 1) * 64, wn0 = (wid >> 1) * 32;
    float acc[4][4][4] = {};

    int a_r = (lane & 15);
    int a_c = (lane >> 4) << 3;
    int b_r = (lane & 7) + ((lane & 16) ? 8 : 0);
    int b_c = (lane & 8) ? 8 : 0;

    for (int s = 0; s < 16; s++) {
        asm volatile("cp.async.wait_group 2;");
        __syncthreads();
        if (s + 3 < 16) issue(s + 3, (s + 3) & 3);
        else            asm volatile("cp.async.commit_group;");

        uint32_t sAu = smem0 + (s & 3) * STG;
        uint32_t sBu = sAu + 2 * PLANE;
        uint32_t bh[2][4], bl[2][4];
        #pragma unroll
        for (int jp = 0; jp < 2; jp++) {
            uint32_t addr = sBu + (uint32_t)(((wn0 + jp * 16 + b_r) * SLDA + b_c) * 2);
            ldsm4(bh[jp], addr);
            ldsm4(bl[jp], addr + PLANE);
        }
        #pragma unroll
        for (int i = 0; i < 4; i++) {
            uint32_t ah[4], al[4];
            uint32_t addr = sAu + (uint32_t)(((wm0 + i * 16 + a_r) * SLDA + a_c) * 2);
            ldsm4(ah, addr);
            ldsm4(al, addr + PLANE);
            #pragma unroll
            for (int j = 0; j < 4; j++) {
                int jp = j >> 1, o = (j & 1) * 2;
                mma16816(acc[i][j], ah, bh[jp][o], bh[jp][o + 1]);
                mma16816(acc[i][j], ah, bl[jp][o], bl[jp][o + 1]);
                mma16816(acc[i][j], al, bh[jp][o], bh[jp][o + 1]);
            }
        }
    }

    int g = lane >> 2, tq = lane & 3;
    if (!mat) {
        float* C = (float*)d_y1;
        #pragma unroll
        for (int j = 0; j < 4; j++) {
            int gcol = n0 + wn0 + j * 8 + tq * 2;
            float bx = b0a[gcol] + b0b[gcol];
            float by = b0a[gcol + 1] + b0b[gcol + 1];
            #pragma unroll
            for (int i = 0; i < 4; i++) {
                int r0 = m0 + wm0 + i * 16 + g;
                if (r0 < NN)
                    *(float2*)&C[(size_t)r0 * 256 + gcol] =
                        make_float2(acc[i][j][0] + bx, acc[i][j][1] + by);
                int r1 = r0 + 8;
                if (r1 < NN)
                    *(float2*)&C[(size_t)r1 * 256 + gcol] =
                        make_float2(acc[i][j][2] + bx, acc[i][j][3] + by);
            }
        }
    } else {
        __half* C = (__half*)d_h1h;
        #pragma unroll
        for (int j = 0; j < 4; j++) {
            int gcol = n0 + wn0 + j * 8 + tq * 2;
            #pragma unroll
            for (int i = 0; i < 4; i++) {
                int r0 = m0 + wm0 + i * 16 + g;
                if (r0 < NN)
                    *(__half2*)&C[(size_t)r0 * 256 + gcol] =
                        __floats2half2_rn(acc[i][j][0], acc[i][j][1]);
                int r1 = r0 + 8;
                if (r1 < NN)
                    *(__half2*)&C[(size_t)r1 * 256 + gcol] =
                        __floats2half2_rn(acc[i][j][2], acc[i][j][3]);
            }
        }
    }
}

// ---------------- layer-1 GAT: warp/dst, shfl-broadcast of precomputed ex, fp16 gather ----------------
__global__ void gat1_warp() {
    int d = (blockIdx.x * blockDim.x + threadIdx.x) >> 5;
    int lane = threadIdx.x & 31;
    if (d >= NN) return;
    int b = d_rowptr[d], e = d_rowptr[d + 1];
    if (b == e) return;
    float4 ald = d_ald1[d];
    int h = lane >> 3;
    int coff = lane * 8;
    float4 acc0 = make_float4(0.f, 0.f, 0.f, 0.f);
    float4 acc1 = make_float4(0.f, 0.f, 0.f, 0.f);
    float den = 0.f;
    const __half* __restrict__ hp = (const __half*)d_h1h;

    for (int c0 = b; c0 < e; c0 += 32) {
        int cnt = min(32, e - c0);
        int src = 0;
        float4 ex = make_float4(0.f, 0.f, 0.f, 0.f);
        if (lane < cnt) {
            src = d_csr_src[c0 + lane];
            float4 a = d_als1[src];
            ex.x = __expf(lrelu(a.x + ald.x));
            ex.y = __expf(lrelu(a.y + ald.y));
            ex.z = __expf(lrelu(a.z + ald.z));
            ex.w = __expf(lrelu(a.w + ald.w));
        }
        #pragma unroll 4
        for (int j = 0; j < cnt; j++) {
            int   sj = __shfl_sync(0xffffffffu, src,  j);
            float e0 = __shfl_sync(0xffffffffu, ex.x, j);
            float e1 = __shfl_sync(0xffffffffu, ex.y, j);
            float e2 = __shfl_sync(0xffffffffu, ex.z, j);
            float e3 = __shfl_sync(0xffffffffu, ex.w, j);
            float w = (h == 0) ? e0 : (h == 1) ? e1 : (h == 2) ? e2 : e3;
            den += w;
            uint4 raw = *(const uint4*)&hp[(size_t)sj * 256 + coff];
            float2 f0 = __half22float2(*(__half2*)&raw.x);
            float2 f1 = __half22float2(*(__half2*)&raw.y);
            float2 f2 = __half22float2(*(__half2*)&raw.z);
            float2 f3 = __half22float2(*(__half2*)&raw.w);
            acc0.x += w * f0.x; acc0.y += w * f0.y;
            acc0.z += w * f1.x; acc0.w += w * f1.y;
            acc1.x += w * f2.x; acc1.y += w * f2.y;
            acc1.z += w * f3.x; acc1.w += w * f3.y;
        }
    }
    float r = 1.f / (den + 1e-16f);
    float4* yp = (float4*)&d_y1[(size_t)d * 256 + coff];
    float4 o0 = yp[0], o1 = yp[1];
    o0.x += acc0.x * r; o0.y += acc0.y * r; o0.z += acc0.z * r; o0.w += acc0.w * r;
    o1.x += acc1.x * r; o1.y += acc1.y * r; o1.z += acc1.z * r; o1.w += acc1.w * r;
    yp[0] = o0; yp[1] = o1;
}

// ---------------- layer 2: fused relu+BN + linear3 + GAT2 features/logits ----------------
__global__ void layer2_row(const float* __restrict__ lin3W, const float* __restrict__ lin3b,
                           const float* __restrict__ con3W, const float* __restrict__ asrc,
                           const float* __restrict__ adst, const float* __restrict__ con3b,
                           float* __restrict__ out) {
    int warp = (blockIdx.x * blockDim.x + threadIdx.x) >> 5;
    int lane = threadIdx.x & 31;
    if (warp >= NN) return;
    const float* row = (const float*)d_y1 + (size_t)warp * 256;
    float y0 = 0.f, y1v = 0.f, h0 = 0.f, h1v = 0.f;
    #pragma unroll
    for (int q = 0; q < 8; q++) {
        int c = lane + q * 32;
        float v = fmaxf(row[c], 0.f) * d_scale[c] + d_shift[c];
        y0  += v * lin3W[c * 2];
        y1v += v * lin3W[c * 2 + 1];
        h0  += v * con3W[c * 2];
        h1v += v * con3W[c * 2 + 1];
    }
    #pragma unroll
    for (int off = 16; off > 0; off >>= 1) {
        y0  += __shfl_xor_sync(0xffffffff, y0,  off);
        y1v += __shfl_xor_sync(0xffffffff, y1v, off);
        h0  += __shfl_xor_sync(0xffffffff, h0,  off);
        h1v += __shfl_xor_sync(0xffffffff, h1v, off);
    }
    if (lane == 0) {
        out[warp * 2]     = y0  + lin3b[0] + con3b[0];
        out[warp * 2 + 1] = y1v + lin3b[1] + con3b[1];
        d_p3[warp] = make_float4(h0 * asrc[0] + h1v * asrc[1],
                                 h0, h1v,
                                 h0 * adst[0] + h1v * adst[1]);
    }
}

// ---------------- layer-2 GAT + final relu (warp/dst, single LDG.128 per edge) ----------------
__global__ void gat_l2(float* __restrict__ out) {
    int d = (blockIdx.x * blockDim.x + threadIdx.x) >> 5;
    int lane = threadIdx.x & 31;
    if (d >= NN) return;
    int b = d_rowptr[d], e = d_rowptr[d + 1];
    float ald = d_p3[d].w;
    float den = 0.f, m0 = 0.f, m1 = 0.f;
    for (int j = b + lane; j < e; j += 32) {
        int src = d_csr_src[j];
        float4 p = d_p3[src];
        float ex = __expf(lrelu(p.x + ald));
        den += ex; m0 += ex * p.y; m1 += ex * p.z;
    }
    #pragma unroll
    for (int off = 16; off > 0; off >>= 1) {
        den += __shfl_xor_sync(0xffffffff, den, off);
        m0  += __shfl_xor_sync(0xffffffff, m0,  off);
        m1  += __shfl_xor_sync(0xffffffff, m1,  off);
    }
    if (lane == 0) {
        float r = 1.f / (den + 1e-16f);
        out[d * 2]     = fmaxf(out[d * 2]     + m0 * r, 0.f);
        out[d * 2 + 1] = fmaxf(out[d * 2 + 1] + m1 * r, 0.f);
    }
}

// ---------------- launch ----------------
extern "C" void kernel_launch(void* const* d_in, const int* in_sizes, int n_in,
                              void* d_out, int out_size) {
    const float* x         = (const float*)d_in[0];
    const int*   ei        = (const int*)d_in[1];
    const float* bn1_g     = (const float*)d_in[2];
    const float* bn1_b     = (const float*)d_in[3];
    const float* lin1_W    = (const float*)d_in[4];
    const float* lin1_b    = (const float*)d_in[5];
    const float* con1_W    = (const float*)d_in[6];
    const float* con1_asrc = (const float*)d_in[7];
    const float* con1_adst = (const float*)d_in[8];
    const float* con1_b    = (const float*)d_in[9];
    const float* bn3_g     = (const float*)d_in[10];
    const float* bn3_b     = (const float*)d_in[11];
    const float* lin3_W    = (const float*)d_in[12];
    const float* lin3_b    = (const float*)d_in[13];
    const float* con3_W    = (const float*)d_in[14];
    const float* con3_asrc = (const float*)d_in[15];
    const float* con3_adst = (const float*)d_in[16];
    const float* con3_b    = (const float*)d_in[17];
    float* out = (float*)d_out;

    const int NCHUNK = (NN + 1 + 1023) / 1024;   // 49

    cudaFuncSetAttribute(gemm_bf16, cudaFuncAttributeMaxDynamicSharedMemorySize, GSMEM);

    // 1-3: BN1 stats/finalize, fused prep (bnconv + wtconv + rowptr zero)
    bn_stats<<<BNPART, 256>>>(x, 0);
    bn_finalize<<<1, 256>>>(bn1_g, bn1_b);
    prep_k<<<PREP_A + PREP_W + PREP_Z, 256>>>(x, lin1_W, con1_W);

    // 4 (ncu-profiled slot): dual GEMM + histogram tail blocks
    gemm_bf16<<<dim3(4, MTILES + HISTROWS), 256, GSMEM>>>(lin1_b, con1_b, ei);

    // 5-6: CSR scan (scan2 folded into scan3), cursor init fused
    scan1_k<<<NCHUNK, 1024>>>();
    scan3_k<<<NCHUNK - 1, 1024>>>();

    // 7: fused scatter + layer-1 logit contributions
    scatter_al_k<<<SCAT_B + AL_B, 256>>>(ei, con1_asrc, con1_adst);

    // 8: warp-per-dst softmax+aggregate (fp16 gather)
    gat1_warp<<<(NN + 7) / 8, 256>>>();

    // 9-10: BN3 stats (relu fused into read), finalize
    bn_stats<<<BNPART, 256>>>(nullptr, 1);
    bn_finalize<<<1, 256>>>(bn3_g, bn3_b);

    // 11-12: layer 2
    layer2_row<<<(NN + 7) / 8, 256>>>(lin3_W, lin3_b, con3_W, con3_asrc, con3_adst, con3_b, out);
    gat_l2<<<(NN + 7) / 8, 256>>>(out);
}